// round 10
// baseline (speedup 1.0000x reference)
#include <cuda_runtime.h>
#include <cuda_fp16.h>
#include <math.h>
#include <stdint.h>

constexpr int Tn = 2048, Dn = 1024, Hn = 16, KVn = 8, HDn = 128, FFn = 3072, Ln = 5;
constexpr float EPSf = 1e-6f;

// ---------------- scratch ----------------
__device__ float g_h [Tn * Dn];
__device__ float g_q [Tn * Hn * HDn];
__device__ float g_kt[Tn * KVn * HDn];
__device__ float g_gate[Tn * FFn];
__device__ float g_up  [Tn * FFn];
__device__ float g_cos[Tn * 64];
__device__ float g_sin[Tn * 64];

__device__ __align__(16) __half g_xh [Tn * Dn];
__device__ __align__(16) __half g_aoh[Tn * Hn * HDn];
__device__ __align__(16) __half g_gh [Tn * FFn];

constexpr size_t W_Q  = 0;
constexpr size_t W_K  = W_Q + (size_t)Ln * Hn * HDn * Dn;
constexpr size_t W_V  = W_K + (size_t)Ln * KVn * HDn * Dn;
constexpr size_t W_O  = W_V + (size_t)Ln * KVn * HDn * Dn;
constexpr size_t W_G  = W_O + (size_t)Ln * Dn * Hn * HDn;
constexpr size_t W_U  = W_G + (size_t)Ln * FFn * Dn;
constexpr size_t W_D  = W_U + (size_t)Ln * FFn * Dn;
constexpr size_t W_TOT= W_D + (size_t)Ln * Dn * FFn;
__device__ __align__(16) __half g_w[W_TOT];

// ---------------- PTX helpers ----------------
__device__ __forceinline__ uint32_t sptr(const void* p) {
    return (uint32_t)__cvta_generic_to_shared(p);
}
__device__ __forceinline__ void ldm_x4(uint32_t* r, uint32_t addr) {
    asm volatile("ldmatrix.sync.aligned.m8n8.x4.shared.b16 {%0,%1,%2,%3}, [%4];"
                 : "=r"(r[0]), "=r"(r[1]), "=r"(r[2]), "=r"(r[3]) : "r"(addr));
}
__device__ __forceinline__ void mma_f16(float* c, const uint32_t* a, uint32_t b0, uint32_t b1) {
    asm volatile("mma.sync.aligned.m16n8k16.row.col.f32.f16.f16.f32 "
                 "{%0,%1,%2,%3}, {%4,%5,%6,%7}, {%8,%9}, {%0,%1,%2,%3};"
                 : "+f"(c[0]), "+f"(c[1]), "+f"(c[2]), "+f"(c[3])
                 : "r"(a[0]), "r"(a[1]), "r"(a[2]), "r"(a[3]), "r"(b0), "r"(b1));
}
__device__ __forceinline__ void cp_async16(uint32_t dst, const void* src) {
    asm volatile("cp.async.ca.shared.global [%0], [%1], 16;" :: "r"(dst), "l"(src));
}
__device__ __forceinline__ void cp_commit() {
    asm volatile("cp.async.commit_group;" ::: "memory");
}
template <int N>
__device__ __forceinline__ void cp_wait() {
    asm volatile("cp.async.wait_group %0;" :: "n"(N) : "memory");
}
__device__ __forceinline__ uint32_t h2u(__half2 h) { return *(uint32_t*)&h; }

// ---------------- weight fp16 conversion ----------------
struct Cv7 {
    const float4* s[7];
    __half* d[7];
    int cum[8];
};
__global__ void conv7_kernel(Cv7 a) {
    int idx = blockIdx.x * 256 + threadIdx.x;
    if (idx >= a.cum[7]) return;
    int s = 0;
#pragma unroll
    for (int i = 0; i < 6; i++) s += (idx >= a.cum[i + 1]) ? 1 : 0;
    int off = idx - a.cum[s];
    float4 v = a.s[s][off];
    ((uint2*)a.d[s])[off] = make_uint2(h2u(__floats2half2_rn(v.x, v.y)),
                                       h2u(__floats2half2_rn(v.z, v.w)));
}

// ---------------- RoPE tables ----------------
__global__ void rope_tables_kernel() {
    int t = blockIdx.x, j = threadIdx.x;
    float inv = 1.0f / powf(1.0e6f, (float)j * (1.0f / 64.0f));
    g_cos[t * 64 + j] = cosf((float)t * inv);
    g_sin[t * 64 + j] = sinf((float)t * inv);
}

// ---------------- RMSNorm rows ----------------
template <int HALF>
__global__ void rms_rows_kernel(const float* __restrict__ in,
                                const float* __restrict__ w,
                                float* __restrict__ out,
                                __half* __restrict__ oh) {
    int t = blockIdx.x;
    const float4* ip = (const float4*)(in + (size_t)t * Dn);
    const float4* wp = (const float4*)w;
    float4 v = ip[threadIdx.x];
    float s = v.x * v.x + v.y * v.y + v.z * v.z + v.w * v.w;
#pragma unroll
    for (int off = 16; off; off >>= 1) s += __shfl_xor_sync(0xffffffffu, s, off);
    __shared__ float ws[8];
    if ((threadIdx.x & 31) == 0) ws[threadIdx.x >> 5] = s;
    __syncthreads();
    float tot = 0.f;
#pragma unroll
    for (int i = 0; i < 8; i++) tot += ws[i];
    float r = rsqrtf(tot * (1.0f / (float)Dn) + EPSf);
    float4 wv = wp[threadIdx.x];
    float4 o = make_float4(v.x * r * wv.x, v.y * r * wv.y, v.z * r * wv.z, v.w * r * wv.w);
    if (HALF) {
        ((uint2*)(oh + (size_t)t * Dn))[threadIdx.x] =
            make_uint2(h2u(__floats2half2_rn(o.x, o.y)),
                       h2u(__floats2half2_rn(o.z, o.w)));
    } else {
        ((float4*)(out + (size_t)t * Dn))[threadIdx.x] = o;
    }
}

// ---------------- combined Q/K per-head RMSNorm + RoPE ----------------
__global__ void qknorm_rope_kernel(float* __restrict__ q,
                                   const float* __restrict__ k,
                                   float* __restrict__ ko,
                                   const float* __restrict__ qw,
                                   const float* __restrict__ kw) {
    int t = blockIdx.x, h = blockIdx.y, d = threadIdx.x;
    bool isq = h < Hn;
    const float* row = isq ? (q + ((size_t)t * Hn + h) * HDn)
                           : (k + ((size_t)t * KVn + (h - Hn)) * HDn);
    const float* w = isq ? qw : kw;
    float v = row[d];
    float s = v * v;
#pragma unroll
    for (int off = 16; off; off >>= 1) s += __shfl_xor_sync(0xffffffffu, s, off);
    __shared__ float ws[4];
    if ((d & 31) == 0) ws[d >> 5] = s;
    __syncthreads();
    float r = rsqrtf((ws[0] + ws[1] + ws[2] + ws[3]) * (1.0f / (float)HDn) + EPSf);
    float xn = v * r * w[d];
    __shared__ float sh[128];
    sh[d] = xn;
    __syncthreads();
    float other = (d < 64) ? -sh[d + 64] : sh[d - 64];
    int j = d & 63;
    float o = xn * g_cos[t * 64 + j] + other * g_sin[t * 64 + j];
    if (isq) q[((size_t)t * Hn + h) * HDn + d] = o;
    else     ko[((size_t)(h - Hn) * Tn + t) * HDn + d] = o;
}

// ---------------- silu(g)*u -> fp16 ----------------
__global__ void silu_mul_kernel(const float4* __restrict__ g, const float4* __restrict__ u,
                                __half* __restrict__ oh, int n4) {
    int idx = blockIdx.x * blockDim.x + threadIdx.x;
    if (idx < n4) {
        float4 gv = g[idx], uv = u[idx];
        float r0 = gv.x / (1.0f + __expf(-gv.x)) * uv.x;
        float r1 = gv.y / (1.0f + __expf(-gv.y)) * uv.y;
        float r2 = gv.z / (1.0f + __expf(-gv.z)) * uv.z;
        float r3 = gv.w / (1.0f + __expf(-gv.w)) * uv.w;
        ((uint2*)oh)[idx] = make_uint2(h2u(__floats2half2_rn(r0, r1)),
                                       h2u(__floats2half2_rn(r2, r3)));
    }
}

// ---------------- fp16 tensor-core GEMM NT (pipelined fragments) ----------------
constexpr int HROWB = 144;
constexpr int ASTB  = 128 * HROWB;
#define HG_SMEM(BN) (3 * (128 + (BN)) * HROWB)

template <int ADD, int BN, int TRANSV>
__device__ __forceinline__ void hgemm_body(const __half* __restrict__ A,
                                           const __half* __restrict__ B,
                                           float* __restrict__ C,
                                           int N, int K, int m0, int n0,
                                           char* smem) {
    constexpr int BSTB = BN * HROWB;
    constexpr int NT2  = BN / 32;
    const int tid = threadIdx.x, lane = tid & 31, wid = tid >> 5;
    const int wm = wid & 3, wn = wid >> 2;

    const __half* Ag = A + (size_t)m0 * K;
    const __half* Bg = B + (size_t)n0 * K;
    const uint32_t sA = sptr(smem);
    const uint32_t sB = sA + 3 * ASTB;

    float acc[2][BN / 16][4];
#pragma unroll
    for (int i = 0; i < 2; i++)
#pragma unroll
        for (int j = 0; j < BN / 16; j++)
#pragma unroll
            for (int q = 0; q < 4; q++) acc[i][j][q] = 0.f;

    const int frow = ((lane >> 3) & 1) * 8 + (lane & 7);
    const int fcol = (lane >> 4) * 16;
    const int nk = K >> 6;

    auto stage = [&](int st, int kt) {
        const __half* Ak = Ag + (size_t)kt * 64;
        const __half* Bk = Bg + (size_t)kt * 64;
        uint32_t da = sA + st * ASTB;
        uint32_t db = sB + st * BSTB;
#pragma unroll
        for (int it = 0; it < 4; ++it) {
            int ch = tid + it * 256;
            int row = ch >> 3, c16 = ch & 7;
            cp_async16(da + row * HROWB + c16 * 16, Ak + (size_t)row * K + c16 * 8);
        }
#pragma unroll
        for (int it = 0; it < BN / 32; ++it) {
            int ch = tid + it * 256;
            int row = ch >> 3, c16 = ch & 7;
            cp_async16(db + row * HROWB + c16 * 16, Bk + (size_t)row * K + c16 * 8);
        }
        cp_commit();
    };

    stage(0, 0);
    if (nk > 1) stage(1, 1);

    for (int i = 0; i < nk; ++i) {
        if (i + 1 < nk) cp_wait<1>(); else cp_wait<0>();
        __syncthreads();
        // global prefetch overlaps this chunk's compute
        if (i + 2 < nk) stage((i + 2) % 3, i + 2);

        const int cur = i % 3;
        const uint32_t aaddr = sA + cur * ASTB + (wm * 32 + frow) * HROWB + fcol;
        const uint32_t baddr = sB + cur * BSTB + (wn * (BN / 2) + frow) * HROWB + fcol;

        // software-pipelined fragments: load ks+1 before mma of ks
        uint32_t af[2][2][4], bf[2][NT2][4];
        ldm_x4(af[0][0], aaddr);
        ldm_x4(af[0][1], aaddr + 16 * HROWB);
#pragma unroll
        for (int n2 = 0; n2 < NT2; ++n2)
            ldm_x4(bf[0][n2], baddr + n2 * 16 * HROWB);
#pragma unroll
        for (int ks = 0; ks < 4; ++ks) {
            const int cb = ks & 1, nb = cb ^ 1;
            if (ks < 3) {
                ldm_x4(af[nb][0], aaddr + (ks + 1) * 32);
                ldm_x4(af[nb][1], aaddr + 16 * HROWB + (ks + 1) * 32);
#pragma unroll
                for (int n2 = 0; n2 < NT2; ++n2)
                    ldm_x4(bf[nb][n2], baddr + n2 * 16 * HROWB + (ks + 1) * 32);
            }
#pragma unroll
            for (int n2 = 0; n2 < NT2; ++n2)
#pragma unroll
                for (int mt = 0; mt < 2; ++mt) {
                    mma_f16(acc[mt][n2 * 2],     af[cb][mt], bf[cb][n2][0], bf[cb][n2][2]);
                    mma_f16(acc[mt][n2 * 2 + 1], af[cb][mt], bf[cb][n2][1], bf[cb][n2][3]);
                }
        }
    }

    const int row0 = m0 + wm * 32 + (lane >> 2);
    const int col0 = n0 + wn * (BN / 2) + (lane & 3) * 2;
#pragma unroll
    for (int mt = 0; mt < 2; ++mt)
#pragma unroll
        for (int nt = 0; nt < BN / 16; ++nt) {
            int r = row0 + mt * 16;
            int c = col0 + nt * 8;
            float2 v0 = make_float2(acc[mt][nt][0], acc[mt][nt][1]);
            float2 v1 = make_float2(acc[mt][nt][2], acc[mt][nt][3]);
            if (TRANSV) {
                *(float2*)&C[((size_t)(c >> 7) * Tn + r) * HDn + (c & 127)] = v0;
                *(float2*)&C[((size_t)(c >> 7) * Tn + (r + 8)) * HDn + (c & 127)] = v1;
            } else {
                float2* p0 = (float2*)&C[(size_t)r * N + c];
                float2* p1 = (float2*)&C[(size_t)(r + 8) * N + c];
                if (ADD) {
                    float2 o0 = *p0, o1 = *p1;
                    v0.x += o0.x; v0.y += o0.y; v1.x += o1.x; v1.y += o1.y;
                }
                *p0 = v0;
                *p1 = v1;
            }
        }
}

__global__ __launch_bounds__(256, 2) void hg_qkv_kernel(
    const __half* __restrict__ xh,
    const __half* __restrict__ wq, const __half* __restrict__ wk, const __half* __restrict__ wv,
    float* __restrict__ q, float* __restrict__ k, float* __restrict__ vlayer) {
    extern __shared__ char smem[];
    int bx = blockIdx.x, m0 = blockIdx.y * 128;
    if (bx < 16)
        hgemm_body<0, 128, 0>(xh, wq, q, Hn * HDn, Dn, m0, bx * 128, smem);
    else if (bx < 24)
        hgemm_body<0, 128, 0>(xh, wk, k, KVn * HDn, Dn, m0, (bx - 16) * 128, smem);
    else
        hgemm_body<0, 128, 1>(xh, wv, vlayer, KVn * HDn, Dn, m0, (bx - 24) * 128, smem);
}

__global__ __launch_bounds__(256, 2) void hg_gu_kernel(
    const __half* __restrict__ xh,
    const __half* __restrict__ wg, const __half* __restrict__ wu,
    float* __restrict__ g, float* __restrict__ u) {
    extern __shared__ char smem[];
    int bx = blockIdx.x, m0 = blockIdx.y * 128;
    if (bx < 24)
        hgemm_body<0, 128, 0>(xh, wg, g, FFn, Dn, m0, bx * 128, smem);
    else
        hgemm_body<0, 128, 0>(xh, wu, u, FFn, Dn, m0, (bx - 24) * 128, smem);
}

__global__ __launch_bounds__(256, 2) void hg_add_kernel(
    const __half* __restrict__ a, const __half* __restrict__ b,
    float* __restrict__ C, int N, int K) {
    extern __shared__ char smem[];
    hgemm_body<1, 64, 0>(a, b, C, N, K, blockIdx.y * 128, blockIdx.x * 64, smem);
}

// ---------------- fp16 MMA flash attention: 128 q-rows, 8 warps ----------------
constexpr int SKH = 136, SVH = 72, SPH = 72;
constexpr int ATTN_SMEM = (64 * SKH + 128 * SVH + 128 * SPH) * 2;  // 54272

__global__ __launch_bounds__(256, 2) void attn_h_kernel(const float* __restrict__ Q,
                                                        const float* __restrict__ Kb,
                                                        const float* __restrict__ Vb,
                                                        __half* __restrict__ AO) {
    extern __shared__ char smraw[];
    __half* sK = (__half*)smraw;
    __half* sV = sK + 64 * SKH;
    __half* sP = sV + 128 * SVH;

    const int h = blockIdx.y;
    const int qt0 = (gridDim.x - 1 - blockIdx.x) * 128;
    const int kv = h >> 1;
    const float scale = 0.0883883476483184f;
    const int tid = threadIdx.x, lane = tid & 31, wid = tid >> 5;
    const int frow = ((lane >> 3) & 1) * 8 + (lane & 7);
    const int fcol = (lane >> 4) * 16;
    const int r0 = lane >> 2, c0 = (lane & 3) * 2;

    uint32_t qf[8][4];
#pragma unroll
    for (int ch = 0; ch < 2; ++ch) {
        __syncthreads();
        const float* qb = Q + (size_t)(qt0 + ch * 64) * (Hn * HDn) + (size_t)h * HDn;
#pragma unroll
        for (int r = 0; r < 8; ++r) {
            int idx = tid + r * 256;
            int row = idx >> 5, c4 = idx & 31;
            float4 v = *(const float4*)(qb + (size_t)row * (Hn * HDn) + c4 * 4);
            *(uint2*)&sK[row * SKH + c4 * 4] =
                make_uint2(h2u(__floats2half2_rn(v.x * scale, v.y * scale)),
                           h2u(__floats2half2_rn(v.z * scale, v.w * scale)));
        }
        __syncthreads();
        if ((wid >> 2) == ch) {
            uint32_t qaddr = sptr(sK) + ((wid & 3) * 16 + frow) * (SKH * 2) + fcol;
#pragma unroll
            for (int ks = 0; ks < 8; ++ks) ldm_x4(qf[ks], qaddr + ks * 32);
        }
    }
    __syncthreads();

    float o[16][4];
#pragma unroll
    for (int i = 0; i < 16; i++)
#pragma unroll
        for (int j = 0; j < 4; j++) o[i][j] = 0.f;
    float mreg[2] = {-1e30f, -1e30f}, lreg[2] = {0.f, 0.f};

    const float* Kh = Kb + (size_t)kv * Tn * HDn;
    const float* Vh = Vb + (size_t)kv * Tn * HDn;
    const int nkt = (qt0 >> 6) + 2;

    __half* myP = sP + wid * 16 * SPH;
    const uint32_t kaddr = sptr(sK) + frow * (SKH * 2) + fcol;
    const uint32_t paddr = sptr(myP) + frow * (SPH * 2) + fcol;
    const uint32_t vaddr = sptr(sV) + frow * (SVH * 2) + fcol;

    for (int kt = 0; kt < nkt; ++kt) {
        const int kt0 = kt << 6;
        if (kt) __syncthreads();
#pragma unroll
        for (int r = 0; r < 8; ++r) {
            int idx = tid + r * 256;
            int row = idx >> 5, c4 = idx & 31;
            float4 v = *(const float4*)(Kh + (size_t)(kt0 + row) * HDn + c4 * 4);
            *(uint2*)&sK[row * SKH + c4 * 4] =
                make_uint2(h2u(__floats2half2_rn(v.x, v.y)),
                           h2u(__floats2half2_rn(v.z, v.w)));
        }
        {
            const int d = tid & 127, half_ = tid >> 7;
#pragma unroll
            for (int rg = 0; rg < 8; ++rg) {
                int kp = half_ * 32 + rg * 4;
                float v0 = Vh[(size_t)(kt0 + kp + 0) * HDn + d];
                float v1 = Vh[(size_t)(kt0 + kp + 1) * HDn + d];
                float v2 = Vh[(size_t)(kt0 + kp + 2) * HDn + d];
                float v3 = Vh[(size_t)(kt0 + kp + 3) * HDn + d];
                *(uint2*)&sV[d * SVH + kp] =
                    make_uint2(h2u(__floats2half2_rn(v0, v1)),
                               h2u(__floats2half2_rn(v2, v3)));
            }
        }
        __syncthreads();

        float s[8][4];
#pragma unroll
        for (int i = 0; i < 8; i++)
#pragma unroll
            for (int j = 0; j < 4; j++) s[i][j] = 0.f;
#pragma unroll
        for (int ks = 0; ks < 8; ++ks) {
#pragma unroll
            for (int ntp = 0; ntp < 4; ++ntp) {
                uint32_t bf[4];
                ldm_x4(bf, kaddr + ntp * 16 * (SKH * 2) + ks * 32);
                mma_f16(s[ntp * 2],     qf[ks], bf[0], bf[2]);
                mma_f16(s[ntp * 2 + 1], qf[ks], bf[1], bf[3]);
            }
        }

        if (kt >= nkt - 2) {
            int rowg = qt0 + wid * 16 + r0;
#pragma unroll
            for (int nt = 0; nt < 8; ++nt) {
                int colg = kt0 + nt * 8 + c0;
                if (colg > rowg)          s[nt][0] = -1e30f;
                if (colg + 1 > rowg)      s[nt][1] = -1e30f;
                if (colg > rowg + 8)      s[nt][2] = -1e30f;
                if (colg + 1 > rowg + 8)  s[nt][3] = -1e30f;
            }
        }

#pragma unroll
        for (int hf = 0; hf < 2; ++hf) {
            float rm = -1e30f;
#pragma unroll
            for (int nt = 0; nt < 8; ++nt)
                rm = fmaxf(rm, fmaxf(s[nt][2 * hf], s[nt][2 * hf + 1]));
            rm = fmaxf(rm, __shfl_xor_sync(0xffffffffu, rm, 1));
            rm = fmaxf(rm, __shfl_xor_sync(0xffffffffu, rm, 2));
            float mn = fmaxf(mreg[hf], rm);
            float corr = __expf(mreg[hf] - mn);
            mreg[hf] = mn;
            float su = 0.f;
#pragma unroll
            for (int nt = 0; nt < 8; ++nt) {
                float e0 = __expf(s[nt][2 * hf] - mn);
                float e1 = __expf(s[nt][2 * hf + 1] - mn);
                s[nt][2 * hf] = e0;
                s[nt][2 * hf + 1] = e1;
                su += e0 + e1;
            }
            su += __shfl_xor_sync(0xffffffffu, su, 1);
            su += __shfl_xor_sync(0xffffffffu, su, 2);
            lreg[hf] = lreg[hf] * corr + su;
#pragma unroll
            for (int nt = 0; nt < 16; ++nt) {
                o[nt][2 * hf] *= corr;
                o[nt][2 * hf + 1] *= corr;
            }
        }

#pragma unroll
        for (int nt = 0; nt < 8; ++nt) {
            *(__half2*)&myP[r0 * SPH + nt * 8 + c0] = __floats2half2_rn(s[nt][0], s[nt][1]);
            *(__half2*)&myP[(r0 + 8) * SPH + nt * 8 + c0] = __floats2half2_rn(s[nt][2], s[nt][3]);
        }
        __syncwarp();

#pragma unroll
        for (int ks = 0; ks < 4; ++ks) {
            uint32_t pf[4];
            ldm_x4(pf, paddr + ks * 32);
#pragma unroll
            for (int np = 0; np < 8; ++np) {
                uint32_t bf[4];
                ldm_x4(bf, vaddr + np * 16 * (SVH * 2) + ks * 32);
                mma_f16(o[2 * np],     pf, bf[0], bf[2]);
                mma_f16(o[2 * np + 1], pf, bf[1], bf[3]);
            }
        }
    }

    float inv0 = 1.0f / lreg[0], inv1 = 1.0f / lreg[1];
    int rowg = qt0 + wid * 16 + r0;
#pragma unroll
    for (int nt = 0; nt < 16; ++nt) {
        size_t base = (size_t)h * HDn + nt * 8 + c0;
        *(__half2*)&AO[(size_t)rowg * (Hn * HDn) + base] =
            __floats2half2_rn(o[nt][0] * inv0, o[nt][1] * inv0);
        *(__half2*)&AO[(size_t)(rowg + 8) * (Hn * HDn) + base] =
            __floats2half2_rn(o[nt][2] * inv1, o[nt][3] * inv1);
    }
}

// ---------------- host orchestration ----------------
extern "C" void kernel_launch(void* const* d_in, const int* in_sizes, int n_in,
                              void* d_out, int out_size) {
    const float* emb = (const float*)d_in[0];
    const float* ln1 = (const float*)d_in[1];
    const float* qw  = (const float*)d_in[2];
    const float* kw  = (const float*)d_in[3];
    const float* vw  = (const float*)d_in[4];
    const float* qn  = (const float*)d_in[5];
    const float* kn  = (const float*)d_in[6];
    const float* ow  = (const float*)d_in[7];
    const float* ln2 = (const float*)d_in[8];
    const float* gw  = (const float*)d_in[9];
    const float* uw  = (const float*)d_in[10];
    const float* dw  = (const float*)d_in[11];
    const float* nw  = (const float*)d_in[12];

    float* out  = (float*)d_out;
    float* keys = out + (size_t)Tn * Dn;
    float* vals = keys + (size_t)Ln * KVn * Tn * HDn;

    float *ph, *pq, *pkt, *pg, *pu;
    __half *pxh, *paoh, *pgh, *pw;
    cudaGetSymbolAddress((void**)&ph,   g_h);
    cudaGetSymbolAddress((void**)&pq,   g_q);
    cudaGetSymbolAddress((void**)&pkt,  g_kt);
    cudaGetSymbolAddress((void**)&pg,   g_gate);
    cudaGetSymbolAddress((void**)&pu,   g_up);
    cudaGetSymbolAddress((void**)&pxh,  g_xh);
    cudaGetSymbolAddress((void**)&paoh, g_aoh);
    cudaGetSymbolAddress((void**)&pgh,  g_gh);
    cudaGetSymbolAddress((void**)&pw,   g_w);

    cudaFuncSetAttribute(attn_h_kernel, cudaFuncAttributeMaxDynamicSharedMemorySize, ATTN_SMEM);
    cudaFuncSetAttribute(hg_qkv_kernel, cudaFuncAttributeMaxDynamicSharedMemorySize, HG_SMEM(128));
    cudaFuncSetAttribute(hg_gu_kernel,  cudaFuncAttributeMaxDynamicSharedMemorySize, HG_SMEM(128));
    cudaFuncSetAttribute(hg_add_kernel, cudaFuncAttributeMaxDynamicSharedMemorySize, HG_SMEM(64));

    {
        Cv7 a;
        size_t offs[7] = { W_Q, W_K, W_V, W_O, W_G, W_U, W_D };
        const float* srcs[7] = { qw, kw, vw, ow, gw, uw, dw };
        size_t ns[7] = {
            (size_t)Ln * Hn * HDn * Dn, (size_t)Ln * KVn * HDn * Dn,
            (size_t)Ln * KVn * HDn * Dn, (size_t)Ln * Dn * Hn * HDn,
            (size_t)Ln * FFn * Dn, (size_t)Ln * FFn * Dn, (size_t)Ln * Dn * FFn };
        int cum = 0;
        for (int i = 0; i < 7; i++) {
            a.s[i] = (const float4*)srcs[i];
            a.d[i] = pw + offs[i];
            a.cum[i] = cum;
            cum += (int)(ns[i] / 4);
        }
        a.cum[7] = cum;
        conv7_kernel<<<(cum + 255) / 256, 256>>>(a);
    }

    cudaMemcpyAsync(ph, emb, sizeof(float) * Tn * Dn, cudaMemcpyDeviceToDevice);
    rope_tables_kernel<<<Tn, 64>>>();

    for (int i = 0; i < Ln; ++i) {
        float* klayer = keys + (size_t)i * KVn * Tn * HDn;
        float* vlayer = vals + (size_t)i * KVn * Tn * HDn;

        rms_rows_kernel<1><<<Tn, 256>>>(ph, ln1 + (size_t)i * Dn, nullptr, pxh);

        hg_qkv_kernel<<<dim3(32, Tn / 128), 256, HG_SMEM(128)>>>(
            pxh,
            pw + W_Q + (size_t)i * (Hn * HDn) * Dn,
            pw + W_K + (size_t)i * (KVn * HDn) * Dn,
            pw + W_V + (size_t)i * (KVn * HDn) * Dn,
            pq, pkt, vlayer);

        qknorm_rope_kernel<<<dim3(Tn, Hn + KVn), 128>>>(
            pq, pkt, klayer, qn + (size_t)i * HDn, kn + (size_t)i * HDn);

        attn_h_kernel<<<dim3(Tn / 128, Hn), 256, ATTN_SMEM>>>(pq, klayer, vlayer, paoh);

        hg_add_kernel<<<dim3(Dn / 64, Tn / 128), 256, HG_SMEM(64)>>>(
            paoh, pw + W_O + (size_t)i * Dn * (Hn * HDn), ph, Dn, Hn * HDn);

        rms_rows_kernel<1><<<Tn, 256>>>(ph, ln2 + (size_t)i * Dn, nullptr, pxh);

        hg_gu_kernel<<<dim3(48, Tn / 128), 256, HG_SMEM(128)>>>(
            pxh,
            pw + W_G + (size_t)i * FFn * Dn,
            pw + W_U + (size_t)i * FFn * Dn,
            pg, pu);

        silu_mul_kernel<<<(Tn * FFn / 4 + 255) / 256, 256>>>(
            (const float4*)pg, (const float4*)pu, pgh, Tn * FFn / 4);

        hg_add_kernel<<<dim3(Dn / 64, Tn / 128), 256, HG_SMEM(64)>>>(
            pgh, pw + W_D + (size_t)i * Dn * FFn, ph, Dn, FFn);
    }

    rms_rows_kernel<0><<<Tn, 256>>>(ph, nw, out, nullptr);
}

// round 11
// speedup vs baseline: 1.1587x; 1.1587x over previous
#include <cuda_runtime.h>
#include <cuda_fp16.h>
#include <math.h>
#include <stdint.h>

constexpr int Tn = 2048, Dn = 1024, Hn = 16, KVn = 8, HDn = 128, FFn = 3072, Ln = 5;
constexpr float EPSf = 1e-6f;

// ---------------- scratch ----------------
__device__ float g_h [Tn * Dn];
__device__ float g_q [Tn * Hn * HDn];
__device__ float g_kt[Tn * KVn * HDn];
__device__ float g_gate[Tn * FFn];
__device__ float g_up  [Tn * FFn];
__device__ float g_cos[Tn * 64];
__device__ float g_sin[Tn * 64];

__device__ __align__(16) __half g_xh [Tn * Dn];
__device__ __align__(16) __half g_aoh[Tn * Hn * HDn];
__device__ __align__(16) __half g_gh [Tn * FFn];

constexpr size_t W_Q  = 0;
constexpr size_t W_K  = W_Q + (size_t)Ln * Hn * HDn * Dn;
constexpr size_t W_V  = W_K + (size_t)Ln * KVn * HDn * Dn;
constexpr size_t W_O  = W_V + (size_t)Ln * KVn * HDn * Dn;
constexpr size_t W_G  = W_O + (size_t)Ln * Dn * Hn * HDn;
constexpr size_t W_U  = W_G + (size_t)Ln * FFn * Dn;
constexpr size_t W_D  = W_U + (size_t)Ln * FFn * Dn;
constexpr size_t W_TOT= W_D + (size_t)Ln * Dn * FFn;
__device__ __align__(16) __half g_w[W_TOT];

// ---------------- PTX helpers ----------------
__device__ __forceinline__ uint32_t sptr(const void* p) {
    return (uint32_t)__cvta_generic_to_shared(p);
}
__device__ __forceinline__ void ldm_x4(uint32_t* r, uint32_t addr) {
    asm volatile("ldmatrix.sync.aligned.m8n8.x4.shared.b16 {%0,%1,%2,%3}, [%4];"
                 : "=r"(r[0]), "=r"(r[1]), "=r"(r[2]), "=r"(r[3]) : "r"(addr));
}
__device__ __forceinline__ void mma_f16(float* c, const uint32_t* a, uint32_t b0, uint32_t b1) {
    asm volatile("mma.sync.aligned.m16n8k16.row.col.f32.f16.f16.f32 "
                 "{%0,%1,%2,%3}, {%4,%5,%6,%7}, {%8,%9}, {%0,%1,%2,%3};"
                 : "+f"(c[0]), "+f"(c[1]), "+f"(c[2]), "+f"(c[3])
                 : "r"(a[0]), "r"(a[1]), "r"(a[2]), "r"(a[3]), "r"(b0), "r"(b1));
}
__device__ __forceinline__ void cp_async16(uint32_t dst, const void* src) {
    asm volatile("cp.async.ca.shared.global [%0], [%1], 16;" :: "r"(dst), "l"(src));
}
__device__ __forceinline__ void cp_commit() {
    asm volatile("cp.async.commit_group;" ::: "memory");
}
template <int N>
__device__ __forceinline__ void cp_wait() {
    asm volatile("cp.async.wait_group %0;" :: "n"(N) : "memory");
}
__device__ __forceinline__ uint32_t h2u(__half2 h) { return *(uint32_t*)&h; }

// ---------------- weight fp16 conversion ----------------
struct Cv7 {
    const float4* s[7];
    __half* d[7];
    int cum[8];
};
__global__ void conv7_kernel(Cv7 a) {
    int idx = blockIdx.x * 256 + threadIdx.x;
    if (idx >= a.cum[7]) return;
    int s = 0;
#pragma unroll
    for (int i = 0; i < 6; i++) s += (idx >= a.cum[i + 1]) ? 1 : 0;
    int off = idx - a.cum[s];
    float4 v = a.s[s][off];
    ((uint2*)a.d[s])[off] = make_uint2(h2u(__floats2half2_rn(v.x, v.y)),
                                       h2u(__floats2half2_rn(v.z, v.w)));
}

// ---------------- RoPE tables ----------------
__global__ void rope_tables_kernel() {
    int t = blockIdx.x, j = threadIdx.x;
    float inv = 1.0f / powf(1.0e6f, (float)j * (1.0f / 64.0f));
    g_cos[t * 64 + j] = cosf((float)t * inv);
    g_sin[t * 64 + j] = sinf((float)t * inv);
}

// ---------------- RMSNorm rows ----------------
template <int HALF>
__global__ void rms_rows_kernel(const float* __restrict__ in,
                                const float* __restrict__ w,
                                float* __restrict__ out,
                                __half* __restrict__ oh) {
    int t = blockIdx.x;
    const float4* ip = (const float4*)(in + (size_t)t * Dn);
    const float4* wp = (const float4*)w;
    float4 v = ip[threadIdx.x];
    float s = v.x * v.x + v.y * v.y + v.z * v.z + v.w * v.w;
#pragma unroll
    for (int off = 16; off; off >>= 1) s += __shfl_xor_sync(0xffffffffu, s, off);
    __shared__ float ws[8];
    if ((threadIdx.x & 31) == 0) ws[threadIdx.x >> 5] = s;
    __syncthreads();
    float tot = 0.f;
#pragma unroll
    for (int i = 0; i < 8; i++) tot += ws[i];
    float r = rsqrtf(tot * (1.0f / (float)Dn) + EPSf);
    float4 wv = wp[threadIdx.x];
    float4 o = make_float4(v.x * r * wv.x, v.y * r * wv.y, v.z * r * wv.z, v.w * r * wv.w);
    if (HALF) {
        ((uint2*)(oh + (size_t)t * Dn))[threadIdx.x] =
            make_uint2(h2u(__floats2half2_rn(o.x, o.y)),
                       h2u(__floats2half2_rn(o.z, o.w)));
    } else {
        ((float4*)(out + (size_t)t * Dn))[threadIdx.x] = o;
    }
}

// ---------------- combined Q/K per-head RMSNorm + RoPE ----------------
__global__ void qknorm_rope_kernel(float* __restrict__ q,
                                   const float* __restrict__ k,
                                   float* __restrict__ ko,
                                   const float* __restrict__ qw,
                                   const float* __restrict__ kw) {
    int t = blockIdx.x, h = blockIdx.y, d = threadIdx.x;
    bool isq = h < Hn;
    const float* row = isq ? (q + ((size_t)t * Hn + h) * HDn)
                           : (k + ((size_t)t * KVn + (h - Hn)) * HDn);
    const float* w = isq ? qw : kw;
    float v = row[d];
    float s = v * v;
#pragma unroll
    for (int off = 16; off; off >>= 1) s += __shfl_xor_sync(0xffffffffu, s, off);
    __shared__ float ws[4];
    if ((d & 31) == 0) ws[d >> 5] = s;
    __syncthreads();
    float r = rsqrtf((ws[0] + ws[1] + ws[2] + ws[3]) * (1.0f / (float)HDn) + EPSf);
    float xn = v * r * w[d];
    __shared__ float sh[128];
    sh[d] = xn;
    __syncthreads();
    float other = (d < 64) ? -sh[d + 64] : sh[d - 64];
    int j = d & 63;
    float o = xn * g_cos[t * 64 + j] + other * g_sin[t * 64 + j];
    if (isq) q[((size_t)t * Hn + h) * HDn + d] = o;
    else     ko[((size_t)(h - Hn) * Tn + t) * HDn + d] = o;
}

// ---------------- silu(g)*u -> fp16 ----------------
__global__ void silu_mul_kernel(const float4* __restrict__ g, const float4* __restrict__ u,
                                __half* __restrict__ oh, int n4) {
    int idx = blockIdx.x * blockDim.x + threadIdx.x;
    if (idx < n4) {
        float4 gv = g[idx], uv = u[idx];
        float r0 = gv.x / (1.0f + __expf(-gv.x)) * uv.x;
        float r1 = gv.y / (1.0f + __expf(-gv.y)) * uv.y;
        float r2 = gv.z / (1.0f + __expf(-gv.z)) * uv.z;
        float r3 = gv.w / (1.0f + __expf(-gv.w)) * uv.w;
        ((uint2*)oh)[idx] = make_uint2(h2u(__floats2half2_rn(r0, r1)),
                                       h2u(__floats2half2_rn(r2, r3)));
    }
}

// ---------------- fp16 tensor-core GEMM NT (2-stage, 2 CTAs/SM) ----------------
constexpr int HROWB = 144;
constexpr int ASTB  = 128 * HROWB;
#define HG_SMEM(BN) (2 * (128 + (BN)) * HROWB)

template <int ADD, int BN, int TRANSV>
__device__ __forceinline__ void hgemm_body(const __half* __restrict__ A,
                                           const __half* __restrict__ B,
                                           float* __restrict__ C,
                                           int N, int K, int m0, int n0,
                                           char* smem) {
    constexpr int BSTB = BN * HROWB;
    constexpr int NT2  = BN / 32;
    const int tid = threadIdx.x, lane = tid & 31, wid = tid >> 5;
    const int wm = wid & 3, wn = wid >> 2;

    const __half* Ag = A + (size_t)m0 * K;
    const __half* Bg = B + (size_t)n0 * K;
    const uint32_t sA = sptr(smem);
    const uint32_t sB = sA + 2 * ASTB;

    float acc[2][BN / 16][4];
#pragma unroll
    for (int i = 0; i < 2; i++)
#pragma unroll
        for (int j = 0; j < BN / 16; j++)
#pragma unroll
            for (int q = 0; q < 4; q++) acc[i][j][q] = 0.f;

    const int frow = ((lane >> 3) & 1) * 8 + (lane & 7);
    const int fcol = (lane >> 4) * 16;
    const int nk = K >> 6;

    auto stage = [&](int st, int kt) {
        const __half* Ak = Ag + (size_t)kt * 64;
        const __half* Bk = Bg + (size_t)kt * 64;
        uint32_t da = sA + st * ASTB;
        uint32_t db = sB + st * BSTB;
#pragma unroll
        for (int it = 0; it < 4; ++it) {
            int ch = tid + it * 256;
            int row = ch >> 3, c16 = ch & 7;
            cp_async16(da + row * HROWB + c16 * 16, Ak + (size_t)row * K + c16 * 8);
        }
#pragma unroll
        for (int it = 0; it < BN / 32; ++it) {
            int ch = tid + it * 256;
            int row = ch >> 3, c16 = ch & 7;
            cp_async16(db + row * HROWB + c16 * 16, Bk + (size_t)row * K + c16 * 8);
        }
        cp_commit();
    };

    stage(0, 0);

    for (int i = 0; i < nk; ++i) {
        cp_wait<0>();
        __syncthreads();
        // prefetch next chunk into the other buffer; overlaps this chunk's mma
        if (i + 1 < nk) stage((i + 1) & 1, i + 1);

        const int cur = i & 1;
        const uint32_t aaddr = sA + cur * ASTB + (wm * 32 + frow) * HROWB + fcol;
        const uint32_t baddr = sB + cur * BSTB + (wn * (BN / 2) + frow) * HROWB + fcol;
#pragma unroll
        for (int ks = 0; ks < 4; ++ks) {
            uint32_t af[2][4];
            ldm_x4(af[0], aaddr + ks * 32);
            ldm_x4(af[1], aaddr + 16 * HROWB + ks * 32);
#pragma unroll
            for (int n2 = 0; n2 < NT2; ++n2) {
                uint32_t bf[4];
                ldm_x4(bf, baddr + n2 * 16 * HROWB + ks * 32);
#pragma unroll
                for (int mt = 0; mt < 2; ++mt) {
                    mma_f16(acc[mt][n2 * 2],     af[mt], bf[0], bf[2]);
                    mma_f16(acc[mt][n2 * 2 + 1], af[mt], bf[1], bf[3]);
                }
            }
        }
    }

    const int row0 = m0 + wm * 32 + (lane >> 2);
    const int col0 = n0 + wn * (BN / 2) + (lane & 3) * 2;
#pragma unroll
    for (int mt = 0; mt < 2; ++mt)
#pragma unroll
        for (int nt = 0; nt < BN / 16; ++nt) {
            int r = row0 + mt * 16;
            int c = col0 + nt * 8;
            float2 v0 = make_float2(acc[mt][nt][0], acc[mt][nt][1]);
            float2 v1 = make_float2(acc[mt][nt][2], acc[mt][nt][3]);
            if (TRANSV) {
                *(float2*)&C[((size_t)(c >> 7) * Tn + r) * HDn + (c & 127)] = v0;
                *(float2*)&C[((size_t)(c >> 7) * Tn + (r + 8)) * HDn + (c & 127)] = v1;
            } else {
                float2* p0 = (float2*)&C[(size_t)r * N + c];
                float2* p1 = (float2*)&C[(size_t)(r + 8) * N + c];
                if (ADD) {
                    float2 o0 = *p0, o1 = *p1;
                    v0.x += o0.x; v0.y += o0.y; v1.x += o1.x; v1.y += o1.y;
                }
                *p0 = v0;
                *p1 = v1;
            }
        }
}

__global__ __launch_bounds__(256, 2) void hg_qkv_kernel(
    const __half* __restrict__ xh,
    const __half* __restrict__ wq, const __half* __restrict__ wk, const __half* __restrict__ wv,
    float* __restrict__ q, float* __restrict__ k, float* __restrict__ vlayer) {
    extern __shared__ char smem[];
    int bx = blockIdx.x, m0 = blockIdx.y * 128;
    if (bx < 16)
        hgemm_body<0, 128, 0>(xh, wq, q, Hn * HDn, Dn, m0, bx * 128, smem);
    else if (bx < 24)
        hgemm_body<0, 128, 0>(xh, wk, k, KVn * HDn, Dn, m0, (bx - 16) * 128, smem);
    else
        hgemm_body<0, 128, 1>(xh, wv, vlayer, KVn * HDn, Dn, m0, (bx - 24) * 128, smem);
}

__global__ __launch_bounds__(256, 2) void hg_gu_kernel(
    const __half* __restrict__ xh,
    const __half* __restrict__ wg, const __half* __restrict__ wu,
    float* __restrict__ g, float* __restrict__ u) {
    extern __shared__ char smem[];
    int bx = blockIdx.x, m0 = blockIdx.y * 128;
    if (bx < 24)
        hgemm_body<0, 128, 0>(xh, wg, g, FFn, Dn, m0, bx * 128, smem);
    else
        hgemm_body<0, 128, 0>(xh, wu, u, FFn, Dn, m0, (bx - 24) * 128, smem);
}

__global__ __launch_bounds__(256, 2) void hg_add_kernel(
    const __half* __restrict__ a, const __half* __restrict__ b,
    float* __restrict__ C, int N, int K) {
    extern __shared__ char smem[];
    hgemm_body<1, 64, 0>(a, b, C, N, K, blockIdx.y * 128, blockIdx.x * 64, smem);
}

// ---------------- fp16 MMA flash attention (unchanged from R9): 128 q-rows, 8 warps ----------------
constexpr int SKH = 136, SVH = 72, SPH = 72;
constexpr int ATTN_SMEM = (64 * SKH + 128 * SVH + 128 * SPH) * 2;  // 54272

__global__ __launch_bounds__(256) void attn_h_kernel(const float* __restrict__ Q,
                                                     const float* __restrict__ Kb,
                                                     const float* __restrict__ Vb,
                                                     __half* __restrict__ AO) {
    extern __shared__ char smraw[];
    __half* sK = (__half*)smraw;
    __half* sV = sK + 64 * SKH;
    __half* sP = sV + 128 * SVH;

    const int h = blockIdx.y;
    const int qt0 = (gridDim.x - 1 - blockIdx.x) * 128;
    const int kv = h >> 1;
    const float scale = 0.0883883476483184f;
    const int tid = threadIdx.x, lane = tid & 31, wid = tid >> 5;
    const int frow = ((lane >> 3) & 1) * 8 + (lane & 7);
    const int fcol = (lane >> 4) * 16;
    const int r0 = lane >> 2, c0 = (lane & 3) * 2;

    uint32_t qf[8][4];
#pragma unroll
    for (int ch = 0; ch < 2; ++ch) {
        __syncthreads();
        const float* qb = Q + (size_t)(qt0 + ch * 64) * (Hn * HDn) + (size_t)h * HDn;
#pragma unroll
        for (int r = 0; r < 8; ++r) {
            int idx = tid + r * 256;
            int row = idx >> 5, c4 = idx & 31;
            float4 v = *(const float4*)(qb + (size_t)row * (Hn * HDn) + c4 * 4);
            *(uint2*)&sK[row * SKH + c4 * 4] =
                make_uint2(h2u(__floats2half2_rn(v.x * scale, v.y * scale)),
                           h2u(__floats2half2_rn(v.z * scale, v.w * scale)));
        }
        __syncthreads();
        if ((wid >> 2) == ch) {
            uint32_t qaddr = sptr(sK) + ((wid & 3) * 16 + frow) * (SKH * 2) + fcol;
#pragma unroll
            for (int ks = 0; ks < 8; ++ks) ldm_x4(qf[ks], qaddr + ks * 32);
        }
    }
    __syncthreads();

    float o[16][4];
#pragma unroll
    for (int i = 0; i < 16; i++)
#pragma unroll
        for (int j = 0; j < 4; j++) o[i][j] = 0.f;
    float mreg[2] = {-1e30f, -1e30f}, lreg[2] = {0.f, 0.f};

    const float* Kh = Kb + (size_t)kv * Tn * HDn;
    const float* Vh = Vb + (size_t)kv * Tn * HDn;
    const int nkt = (qt0 >> 6) + 2;

    __half* myP = sP + wid * 16 * SPH;
    const uint32_t kaddr = sptr(sK) + frow * (SKH * 2) + fcol;
    const uint32_t paddr = sptr(myP) + frow * (SPH * 2) + fcol;
    const uint32_t vaddr = sptr(sV) + frow * (SVH * 2) + fcol;

    for (int kt = 0; kt < nkt; ++kt) {
        const int kt0 = kt << 6;
        if (kt) __syncthreads();
#pragma unroll
        for (int r = 0; r < 8; ++r) {
            int idx = tid + r * 256;
            int row = idx >> 5, c4 = idx & 31;
            float4 v = *(const float4*)(Kh + (size_t)(kt0 + row) * HDn + c4 * 4);
            *(uint2*)&sK[row * SKH + c4 * 4] =
                make_uint2(h2u(__floats2half2_rn(v.x, v.y)),
                           h2u(__floats2half2_rn(v.z, v.w)));
        }
        {
            const int d = tid & 127, half_ = tid >> 7;
#pragma unroll
            for (int rg = 0; rg < 8; ++rg) {
                int kp = half_ * 32 + rg * 4;
                float v0 = Vh[(size_t)(kt0 + kp + 0) * HDn + d];
                float v1 = Vh[(size_t)(kt0 + kp + 1) * HDn + d];
                float v2 = Vh[(size_t)(kt0 + kp + 2) * HDn + d];
                float v3 = Vh[(size_t)(kt0 + kp + 3) * HDn + d];
                *(uint2*)&sV[d * SVH + kp] =
                    make_uint2(h2u(__floats2half2_rn(v0, v1)),
                               h2u(__floats2half2_rn(v2, v3)));
            }
        }
        __syncthreads();

        float s[8][4];
#pragma unroll
        for (int i = 0; i < 8; i++)
#pragma unroll
            for (int j = 0; j < 4; j++) s[i][j] = 0.f;
#pragma unroll
        for (int ks = 0; ks < 8; ++ks) {
#pragma unroll
            for (int ntp = 0; ntp < 4; ++ntp) {
                uint32_t bf[4];
                ldm_x4(bf, kaddr + ntp * 16 * (SKH * 2) + ks * 32);
                mma_f16(s[ntp * 2],     qf[ks], bf[0], bf[2]);
                mma_f16(s[ntp * 2 + 1], qf[ks], bf[1], bf[3]);
            }
        }

        if (kt >= nkt - 2) {
            int rowg = qt0 + wid * 16 + r0;
#pragma unroll
            for (int nt = 0; nt < 8; ++nt) {
                int colg = kt0 + nt * 8 + c0;
                if (colg > rowg)          s[nt][0] = -1e30f;
                if (colg + 1 > rowg)      s[nt][1] = -1e30f;
                if (colg > rowg + 8)      s[nt][2] = -1e30f;
                if (colg + 1 > rowg + 8)  s[nt][3] = -1e30f;
            }
        }

#pragma unroll
        for (int hf = 0; hf < 2; ++hf) {
            float rm = -1e30f;
#pragma unroll
            for (int nt = 0; nt < 8; ++nt)
                rm = fmaxf(rm, fmaxf(s[nt][2 * hf], s[nt][2 * hf + 1]));
            rm = fmaxf(rm, __shfl_xor_sync(0xffffffffu, rm, 1));
            rm = fmaxf(rm, __shfl_xor_sync(0xffffffffu, rm, 2));
            float mn = fmaxf(mreg[hf], rm);
            float corr = __expf(mreg[hf] - mn);
            mreg[hf] = mn;
            float su = 0.f;
#pragma unroll
            for (int nt = 0; nt < 8; ++nt) {
                float e0 = __expf(s[nt][2 * hf] - mn);
                float e1 = __expf(s[nt][2 * hf + 1] - mn);
                s[nt][2 * hf] = e0;
                s[nt][2 * hf + 1] = e1;
                su += e0 + e1;
            }
            su += __shfl_xor_sync(0xffffffffu, su, 1);
            su += __shfl_xor_sync(0xffffffffu, su, 2);
            lreg[hf] = lreg[hf] * corr + su;
#pragma unroll
            for (int nt = 0; nt < 16; ++nt) {
                o[nt][2 * hf] *= corr;
                o[nt][2 * hf + 1] *= corr;
            }
        }

#pragma unroll
        for (int nt = 0; nt < 8; ++nt) {
            *(__half2*)&myP[r0 * SPH + nt * 8 + c0] = __floats2half2_rn(s[nt][0], s[nt][1]);
            *(__half2*)&myP[(r0 + 8) * SPH + nt * 8 + c0] = __floats2half2_rn(s[nt][2], s[nt][3]);
        }
        __syncwarp();

#pragma unroll
        for (int ks = 0; ks < 4; ++ks) {
            uint32_t pf[4];
            ldm_x4(pf, paddr + ks * 32);
#pragma unroll
            for (int np = 0; np < 8; ++np) {
                uint32_t bf[4];
                ldm_x4(bf, vaddr + np * 16 * (SVH * 2) + ks * 32);
                mma_f16(o[2 * np],     pf, bf[0], bf[2]);
                mma_f16(o[2 * np + 1], pf, bf[1], bf[3]);
            }
        }
    }

    float inv0 = 1.0f / lreg[0], inv1 = 1.0f / lreg[1];
    int rowg = qt0 + wid * 16 + r0;
#pragma unroll
    for (int nt = 0; nt < 16; ++nt) {
        size_t base = (size_t)h * HDn + nt * 8 + c0;
        *(__half2*)&AO[(size_t)rowg * (Hn * HDn) + base] =
            __floats2half2_rn(o[nt][0] * inv0, o[nt][1] * inv0);
        *(__half2*)&AO[(size_t)(rowg + 8) * (Hn * HDn) + base] =
            __floats2half2_rn(o[nt][2] * inv1, o[nt][3] * inv1);
    }
}

// ---------------- host orchestration ----------------
extern "C" void kernel_launch(void* const* d_in, const int* in_sizes, int n_in,
                              void* d_out, int out_size) {
    const float* emb = (const float*)d_in[0];
    const float* ln1 = (const float*)d_in[1];
    const float* qw  = (const float*)d_in[2];
    const float* kw  = (const float*)d_in[3];
    const float* vw  = (const float*)d_in[4];
    const float* qn  = (const float*)d_in[5];
    const float* kn  = (const float*)d_in[6];
    const float* ow  = (const float*)d_in[7];
    const float* ln2 = (const float*)d_in[8];
    const float* gw  = (const float*)d_in[9];
    const float* uw  = (const float*)d_in[10];
    const float* dw  = (const float*)d_in[11];
    const float* nw  = (const float*)d_in[12];

    float* out  = (float*)d_out;
    float* keys = out + (size_t)Tn * Dn;
    float* vals = keys + (size_t)Ln * KVn * Tn * HDn;

    float *ph, *pq, *pkt, *pg, *pu;
    __half *pxh, *paoh, *pgh, *pw;
    cudaGetSymbolAddress((void**)&ph,   g_h);
    cudaGetSymbolAddress((void**)&pq,   g_q);
    cudaGetSymbolAddress((void**)&pkt,  g_kt);
    cudaGetSymbolAddress((void**)&pg,   g_gate);
    cudaGetSymbolAddress((void**)&pu,   g_up);
    cudaGetSymbolAddress((void**)&pxh,  g_xh);
    cudaGetSymbolAddress((void**)&paoh, g_aoh);
    cudaGetSymbolAddress((void**)&pgh,  g_gh);
    cudaGetSymbolAddress((void**)&pw,   g_w);

    cudaFuncSetAttribute(attn_h_kernel, cudaFuncAttributeMaxDynamicSharedMemorySize, ATTN_SMEM);
    cudaFuncSetAttribute(hg_qkv_kernel, cudaFuncAttributeMaxDynamicSharedMemorySize, HG_SMEM(128));
    cudaFuncSetAttribute(hg_gu_kernel,  cudaFuncAttributeMaxDynamicSharedMemorySize, HG_SMEM(128));
    cudaFuncSetAttribute(hg_add_kernel, cudaFuncAttributeMaxDynamicSharedMemorySize, HG_SMEM(64));

    {
        Cv7 a;
        size_t offs[7] = { W_Q, W_K, W_V, W_O, W_G, W_U, W_D };
        const float* srcs[7] = { qw, kw, vw, ow, gw, uw, dw };
        size_t ns[7] = {
            (size_t)Ln * Hn * HDn * Dn, (size_t)Ln * KVn * HDn * Dn,
            (size_t)Ln * KVn * HDn * Dn, (size_t)Ln * Dn * Hn * HDn,
            (size_t)Ln * FFn * Dn, (size_t)Ln * FFn * Dn, (size_t)Ln * Dn * FFn };
        int cum = 0;
        for (int i = 0; i < 7; i++) {
            a.s[i] = (const float4*)srcs[i];
            a.d[i] = pw + offs[i];
            a.cum[i] = cum;
            cum += (int)(ns[i] / 4);
        }
        a.cum[7] = cum;
        conv7_kernel<<<(cum + 255) / 256, 256>>>(a);
    }

    cudaMemcpyAsync(ph, emb, sizeof(float) * Tn * Dn, cudaMemcpyDeviceToDevice);
    rope_tables_kernel<<<Tn, 64>>>();

    for (int i = 0; i < Ln; ++i) {
        float* klayer = keys + (size_t)i * KVn * Tn * HDn;
        float* vlayer = vals + (size_t)i * KVn * Tn * HDn;

        rms_rows_kernel<1><<<Tn, 256>>>(ph, ln1 + (size_t)i * Dn, nullptr, pxh);

        hg_qkv_kernel<<<dim3(32, Tn / 128), 256, HG_SMEM(128)>>>(
            pxh,
            pw + W_Q + (size_t)i * (Hn * HDn) * Dn,
            pw + W_K + (size_t)i * (KVn * HDn) * Dn,
            pw + W_V + (size_t)i * (KVn * HDn) * Dn,
            pq, pkt, vlayer);

        qknorm_rope_kernel<<<dim3(Tn, Hn + KVn), 128>>>(
            pq, pkt, klayer, qn + (size_t)i * HDn, kn + (size_t)i * HDn);

        attn_h_kernel<<<dim3(Tn / 128, Hn), 256, ATTN_SMEM>>>(pq, klayer, vlayer, paoh);

        hg_add_kernel<<<dim3(Dn / 64, Tn / 128), 256, HG_SMEM(64)>>>(
            paoh, pw + W_O + (size_t)i * Dn * (Hn * HDn), ph, Dn, Hn * HDn);

        rms_rows_kernel<1><<<Tn, 256>>>(ph, ln2 + (size_t)i * Dn, nullptr, pxh);

        hg_gu_kernel<<<dim3(48, Tn / 128), 256, HG_SMEM(128)>>>(
            pxh,
            pw + W_G + (size_t)i * FFn * Dn,
            pw + W_U + (size_t)i * FFn * Dn,
            pg, pu);

        silu_mul_kernel<<<(Tn * FFn / 4 + 255) / 256, 256>>>(
            (const float4*)pg, (const float4*)pu, pgh, Tn * FFn / 4);

        hg_add_kernel<<<dim3(Dn / 64, Tn / 128), 256, HG_SMEM(64)>>>(
            pgh, pw + W_D + (size_t)i * Dn * FFn, ph, Dn, FFn);
    }

    rms_rows_kernel<0><<<Tn, 256>>>(ph, nw, out, nullptr);
}

// round 12
// speedup vs baseline: 1.2734x; 1.0990x over previous
#include <cuda_runtime.h>
#include <cuda_fp16.h>
#include <math.h>
#include <stdint.h>

constexpr int Tn = 2048, Dn = 1024, Hn = 16, KVn = 8, HDn = 128, FFn = 3072, Ln = 5;
constexpr float EPSf = 1e-6f;

// ---------------- scratch ----------------
__device__ float g_h [Tn * Dn];
__device__ float g_q [Tn * Hn * HDn];
__device__ float g_kt[Tn * KVn * HDn];
__device__ float g_gate[Tn * FFn];
__device__ float g_up  [Tn * FFn];
__device__ float g_cos[Tn * 64];
__device__ float g_sin[Tn * 64];

__device__ __align__(16) __half g_xh  [Tn * Dn];
__device__ __align__(16) __half g_aoh [Tn * Hn * HDn];
__device__ __align__(16) __half g_gh  [Tn * FFn];
__device__ __align__(16) __half g_q16 [Tn * Hn * HDn];   // rope'd, pre-scaled fp16 Q
__device__ __align__(16) __half g_k16 [KVn * Tn * HDn];  // rope'd fp16 K (layer-local)
__device__ __align__(16) __half g_vt16[KVn * HDn * Tn];  // fp16 V transposed [kv][d][t]

constexpr size_t W_Q  = 0;
constexpr size_t W_K  = W_Q + (size_t)Ln * Hn * HDn * Dn;
constexpr size_t W_V  = W_K + (size_t)Ln * KVn * HDn * Dn;
constexpr size_t W_O  = W_V + (size_t)Ln * KVn * HDn * Dn;
constexpr size_t W_G  = W_O + (size_t)Ln * Dn * Hn * HDn;
constexpr size_t W_U  = W_G + (size_t)Ln * FFn * Dn;
constexpr size_t W_D  = W_U + (size_t)Ln * FFn * Dn;
constexpr size_t W_TOT= W_D + (size_t)Ln * Dn * FFn;
__device__ __align__(16) __half g_w[W_TOT];

// ---------------- PTX helpers ----------------
__device__ __forceinline__ uint32_t sptr(const void* p) {
    return (uint32_t)__cvta_generic_to_shared(p);
}
__device__ __forceinline__ void ldm_x4(uint32_t* r, uint32_t addr) {
    asm volatile("ldmatrix.sync.aligned.m8n8.x4.shared.b16 {%0,%1,%2,%3}, [%4];"
                 : "=r"(r[0]), "=r"(r[1]), "=r"(r[2]), "=r"(r[3]) : "r"(addr));
}
__device__ __forceinline__ void mma_f16(float* c, const uint32_t* a, uint32_t b0, uint32_t b1) {
    asm volatile("mma.sync.aligned.m16n8k16.row.col.f32.f16.f16.f32 "
                 "{%0,%1,%2,%3}, {%4,%5,%6,%7}, {%8,%9}, {%0,%1,%2,%3};"
                 : "+f"(c[0]), "+f"(c[1]), "+f"(c[2]), "+f"(c[3])
                 : "r"(a[0]), "r"(a[1]), "r"(a[2]), "r"(a[3]), "r"(b0), "r"(b1));
}
__device__ __forceinline__ void cp_async16(uint32_t dst, const void* src) {
    asm volatile("cp.async.ca.shared.global [%0], [%1], 16;" :: "r"(dst), "l"(src));
}
__device__ __forceinline__ void cp_commit() {
    asm volatile("cp.async.commit_group;" ::: "memory");
}
template <int N>
__device__ __forceinline__ void cp_wait() {
    asm volatile("cp.async.wait_group %0;" :: "n"(N) : "memory");
}
__device__ __forceinline__ uint32_t h2u(__half2 h) { return *(uint32_t*)&h; }

// ---------------- weight fp16 conversion ----------------
struct Cv7 {
    const float4* s[7];
    __half* d[7];
    int cum[8];
};
__global__ void conv7_kernel(Cv7 a) {
    int idx = blockIdx.x * 256 + threadIdx.x;
    if (idx >= a.cum[7]) return;
    int s = 0;
#pragma unroll
    for (int i = 0; i < 6; i++) s += (idx >= a.cum[i + 1]) ? 1 : 0;
    int off = idx - a.cum[s];
    float4 v = a.s[s][off];
    ((uint2*)a.d[s])[off] = make_uint2(h2u(__floats2half2_rn(v.x, v.y)),
                                       h2u(__floats2half2_rn(v.z, v.w)));
}

// ---------------- RoPE tables ----------------
__global__ void rope_tables_kernel() {
    int t = blockIdx.x, j = threadIdx.x;
    float inv = 1.0f / powf(1.0e6f, (float)j * (1.0f / 64.0f));
    g_cos[t * 64 + j] = cosf((float)t * inv);
    g_sin[t * 64 + j] = sinf((float)t * inv);
}

// ---------------- RMSNorm rows ----------------
template <int HALF>
__global__ void rms_rows_kernel(const float* __restrict__ in,
                                const float* __restrict__ w,
                                float* __restrict__ out,
                                __half* __restrict__ oh) {
    int t = blockIdx.x;
    const float4* ip = (const float4*)(in + (size_t)t * Dn);
    const float4* wp = (const float4*)w;
    float4 v = ip[threadIdx.x];
    float s = v.x * v.x + v.y * v.y + v.z * v.z + v.w * v.w;
#pragma unroll
    for (int off = 16; off; off >>= 1) s += __shfl_xor_sync(0xffffffffu, s, off);
    __shared__ float ws[8];
    if ((threadIdx.x & 31) == 0) ws[threadIdx.x >> 5] = s;
    __syncthreads();
    float tot = 0.f;
#pragma unroll
    for (int i = 0; i < 8; i++) tot += ws[i];
    float r = rsqrtf(tot * (1.0f / (float)Dn) + EPSf);
    float4 wv = wp[threadIdx.x];
    float4 o = make_float4(v.x * r * wv.x, v.y * r * wv.y, v.z * r * wv.z, v.w * r * wv.w);
    if (HALF) {
        ((uint2*)(oh + (size_t)t * Dn))[threadIdx.x] =
            make_uint2(h2u(__floats2half2_rn(o.x, o.y)),
                       h2u(__floats2half2_rn(o.z, o.w)));
    } else {
        ((float4*)(out + (size_t)t * Dn))[threadIdx.x] = o;
    }
}

// ---------------- combined Q/K per-head RMSNorm + RoPE ----------------
// q -> q16 (fp16, pre-scaled); k -> klayer fp32 (output) + k16 fp16
__global__ void qknorm_rope_kernel(const float* __restrict__ q,
                                   const float* __restrict__ k,
                                   float* __restrict__ ko,
                                   __half* __restrict__ q16,
                                   __half* __restrict__ k16,
                                   const float* __restrict__ qw,
                                   const float* __restrict__ kw) {
    int t = blockIdx.x, h = blockIdx.y, d = threadIdx.x;
    bool isq = h < Hn;
    const float* row = isq ? (q + ((size_t)t * Hn + h) * HDn)
                           : (k + ((size_t)t * KVn + (h - Hn)) * HDn);
    const float* w = isq ? qw : kw;
    float v = row[d];
    float s = v * v;
#pragma unroll
    for (int off = 16; off; off >>= 1) s += __shfl_xor_sync(0xffffffffu, s, off);
    __shared__ float ws[4];
    if ((d & 31) == 0) ws[d >> 5] = s;
    __syncthreads();
    float r = rsqrtf((ws[0] + ws[1] + ws[2] + ws[3]) * (1.0f / (float)HDn) + EPSf);
    float xn = v * r * w[d];
    __shared__ float sh[128];
    sh[d] = xn;
    __syncthreads();
    float other = (d < 64) ? -sh[d + 64] : sh[d - 64];
    int j = d & 63;
    float o = xn * g_cos[t * 64 + j] + other * g_sin[t * 64 + j];
    if (isq) {
        q16[((size_t)t * Hn + h) * HDn + d] = __float2half(o * 0.0883883476483184f);
    } else {
        size_t idx = ((size_t)(h - Hn) * Tn + t) * HDn + d;
        ko[idx] = o;
        k16[idx] = __float2half(o);
    }
}

// ---------------- silu(g)*u -> fp16 ----------------
__global__ void silu_mul_kernel(const float4* __restrict__ g, const float4* __restrict__ u,
                                __half* __restrict__ oh, int n4) {
    int idx = blockIdx.x * blockDim.x + threadIdx.x;
    if (idx < n4) {
        float4 gv = g[idx], uv = u[idx];
        float r0 = gv.x / (1.0f + __expf(-gv.x)) * uv.x;
        float r1 = gv.y / (1.0f + __expf(-gv.y)) * uv.y;
        float r2 = gv.z / (1.0f + __expf(-gv.z)) * uv.z;
        float r3 = gv.w / (1.0f + __expf(-gv.w)) * uv.w;
        ((uint2*)oh)[idx] = make_uint2(h2u(__floats2half2_rn(r0, r1)),
                                       h2u(__floats2half2_rn(r2, r3)));
    }
}

// ---------------- fp16 tensor-core GEMM NT (2-stage, 2 CTAs/SM) ----------------
constexpr int HROWB = 144;
constexpr int ASTB  = 128 * HROWB;
#define HG_SMEM(BN) (2 * (128 + (BN)) * HROWB)

template <int ADD, int BN, int TRANSV>
__device__ __forceinline__ void hgemm_body(const __half* __restrict__ A,
                                           const __half* __restrict__ B,
                                           float* __restrict__ C,
                                           __half* __restrict__ Cv,
                                           int N, int K, int m0, int n0,
                                           char* smem) {
    constexpr int BSTB = BN * HROWB;
    constexpr int NT2  = BN / 32;
    const int tid = threadIdx.x, lane = tid & 31, wid = tid >> 5;
    const int wm = wid & 3, wn = wid >> 2;

    const __half* Ag = A + (size_t)m0 * K;
    const __half* Bg = B + (size_t)n0 * K;
    const uint32_t sA = sptr(smem);
    const uint32_t sB = sA + 2 * ASTB;

    float acc[2][BN / 16][4];
#pragma unroll
    for (int i = 0; i < 2; i++)
#pragma unroll
        for (int j = 0; j < BN / 16; j++)
#pragma unroll
            for (int q = 0; q < 4; q++) acc[i][j][q] = 0.f;

    const int frow = ((lane >> 3) & 1) * 8 + (lane & 7);
    const int fcol = (lane >> 4) * 16;
    const int nk = K >> 6;

    auto stage = [&](int st, int kt) {
        const __half* Ak = Ag + (size_t)kt * 64;
        const __half* Bk = Bg + (size_t)kt * 64;
        uint32_t da = sA + st * ASTB;
        uint32_t db = sB + st * BSTB;
#pragma unroll
        for (int it = 0; it < 4; ++it) {
            int ch = tid + it * 256;
            int row = ch >> 3, c16 = ch & 7;
            cp_async16(da + row * HROWB + c16 * 16, Ak + (size_t)row * K + c16 * 8);
        }
#pragma unroll
        for (int it = 0; it < BN / 32; ++it) {
            int ch = tid + it * 256;
            int row = ch >> 3, c16 = ch & 7;
            cp_async16(db + row * HROWB + c16 * 16, Bk + (size_t)row * K + c16 * 8);
        }
        cp_commit();
    };

    stage(0, 0);

    for (int i = 0; i < nk; ++i) {
        cp_wait<0>();
        __syncthreads();
        if (i + 1 < nk) stage((i + 1) & 1, i + 1);

        const int cur = i & 1;
        const uint32_t aaddr = sA + cur * ASTB + (wm * 32 + frow) * HROWB + fcol;
        const uint32_t baddr = sB + cur * BSTB + (wn * (BN / 2) + frow) * HROWB + fcol;
#pragma unroll
        for (int ks = 0; ks < 4; ++ks) {
            uint32_t af[2][4];
            ldm_x4(af[0], aaddr + ks * 32);
            ldm_x4(af[1], aaddr + 16 * HROWB + ks * 32);
#pragma unroll
            for (int n2 = 0; n2 < NT2; ++n2) {
                uint32_t bf[4];
                ldm_x4(bf, baddr + n2 * 16 * HROWB + ks * 32);
#pragma unroll
                for (int mt = 0; mt < 2; ++mt) {
                    mma_f16(acc[mt][n2 * 2],     af[mt], bf[0], bf[2]);
                    mma_f16(acc[mt][n2 * 2 + 1], af[mt], bf[1], bf[3]);
                }
            }
        }
    }

    const int row0 = m0 + wm * 32 + (lane >> 2);
    const int col0 = n0 + wn * (BN / 2) + (lane & 3) * 2;
#pragma unroll
    for (int mt = 0; mt < 2; ++mt)
#pragma unroll
        for (int nt = 0; nt < BN / 16; ++nt) {
            int r = row0 + mt * 16;
            int c = col0 + nt * 8;
            float2 v0 = make_float2(acc[mt][nt][0], acc[mt][nt][1]);
            float2 v1 = make_float2(acc[mt][nt][2], acc[mt][nt][3]);
            if (TRANSV) {
                // fp32 vals output [kv][t][d]
                *(float2*)&C[((size_t)(c >> 7) * Tn + r) * HDn + (c & 127)] = v0;
                *(float2*)&C[((size_t)(c >> 7) * Tn + (r + 8)) * HDn + (c & 127)] = v1;
                // fp16 V^T copy [kv][d][t]
                size_t vb = ((size_t)(c >> 7) * HDn + (c & 127)) * Tn;
                Cv[vb + r]            = __float2half(v0.x);
                Cv[vb + Tn + r]       = __float2half(v0.y);
                Cv[vb + r + 8]        = __float2half(v1.x);
                Cv[vb + Tn + r + 8]   = __float2half(v1.y);
            } else {
                float2* p0 = (float2*)&C[(size_t)r * N + c];
                float2* p1 = (float2*)&C[(size_t)(r + 8) * N + c];
                if (ADD) {
                    float2 o0 = *p0, o1 = *p1;
                    v0.x += o0.x; v0.y += o0.y; v1.x += o1.x; v1.y += o1.y;
                }
                *p0 = v0;
                *p1 = v1;
            }
        }
}

__global__ __launch_bounds__(256, 2) void hg_qkv_kernel(
    const __half* __restrict__ xh,
    const __half* __restrict__ wq, const __half* __restrict__ wk, const __half* __restrict__ wv,
    float* __restrict__ q, float* __restrict__ k, float* __restrict__ vlayer,
    __half* __restrict__ vt16) {
    extern __shared__ char smem[];
    int bx = blockIdx.x, m0 = blockIdx.y * 128;
    if (bx < 16)
        hgemm_body<0, 128, 0>(xh, wq, q, nullptr, Hn * HDn, Dn, m0, bx * 128, smem);
    else if (bx < 24)
        hgemm_body<0, 128, 0>(xh, wk, k, nullptr, KVn * HDn, Dn, m0, (bx - 16) * 128, smem);
    else
        hgemm_body<0, 128, 1>(xh, wv, vlayer, vt16, KVn * HDn, Dn, m0, (bx - 24) * 128, smem);
}

__global__ __launch_bounds__(256, 2) void hg_gu_kernel(
    const __half* __restrict__ xh,
    const __half* __restrict__ wg, const __half* __restrict__ wu,
    float* __restrict__ g, float* __restrict__ u) {
    extern __shared__ char smem[];
    int bx = blockIdx.x, m0 = blockIdx.y * 128;
    if (bx < 24)
        hgemm_body<0, 128, 0>(xh, wg, g, nullptr, FFn, Dn, m0, bx * 128, smem);
    else
        hgemm_body<0, 128, 0>(xh, wu, u, nullptr, FFn, Dn, m0, (bx - 24) * 128, smem);
}

__global__ __launch_bounds__(256, 2) void hg_add_kernel(
    const __half* __restrict__ a, const __half* __restrict__ b,
    float* __restrict__ C, int N, int K) {
    extern __shared__ char smem[];
    hgemm_body<1, 64, 0>(a, b, C, nullptr, N, K, blockIdx.y * 128, blockIdx.x * 64, smem);
}

// ---------------- fp16 flash attention with cp.async pipelined K/V ----------------
constexpr int SKH = 136;                       // K/Q smem row stride in halves (272B)
constexpr int SVH = 72;                        // V^T row stride in halves (144B)
constexpr int SPH = 72;
constexpr int KTB = 64 * SKH * 2;              // 17408 B per K tile
constexpr int VTB = 128 * SVH * 2;             // 18432 B per V tile
constexpr int QSTB = 128 * SKH * 2;            // 34816 B Q staging (aliases P)
constexpr int ATTN_SMEM = QSTB + 2 * KTB + 2 * VTB;  // 106496 B

__global__ __launch_bounds__(256) void attn_h_kernel(const __half* __restrict__ Q16,
                                                     const __half* __restrict__ K16,
                                                     const __half* __restrict__ VT16,
                                                     __half* __restrict__ AO) {
    extern __shared__ char smraw[];
    const uint32_t sQ = sptr(smraw);           // Q staging; later reused as P
    const uint32_t sKb = sQ + QSTB;
    const uint32_t sVb = sKb + 2 * KTB;

    const int h = blockIdx.y;
    const int qt0 = (gridDim.x - 1 - blockIdx.x) * 128;  // heavy tiles first
    const int kv = h >> 1;
    const int tid = threadIdx.x, lane = tid & 31, wid = tid >> 5;
    const int frow = ((lane >> 3) & 1) * 8 + (lane & 7);
    const int fcol = (lane >> 4) * 16;
    const int r0 = lane >> 2, c0 = (lane & 3) * 2;
    const int nkt = (qt0 >> 6) + 2;

    const char* kbase = (const char*)(K16 + (size_t)kv * Tn * HDn);
    const char* vbase = (const char*)(VT16 + (size_t)kv * HDn * Tn);

    auto stageKV = [&](int kt) {
        const int kt0 = kt << 6;
        uint32_t kb = sKb + (kt & 1) * KTB;
        uint32_t vb = sVb + (kt & 1) * VTB;
        const char* ks = kbase + (size_t)kt0 * (HDn * 2);
#pragma unroll
        for (int it = 0; it < 4; ++it) {
            int ch = tid + it * 256;
            int row = ch >> 4, c = ch & 15;
            cp_async16(kb + row * (SKH * 2) + c * 16, ks + (size_t)row * 256 + c * 16);
        }
        const char* vs = vbase + (size_t)kt0 * 2;
#pragma unroll
        for (int it = 0; it < 4; ++it) {
            int ch = tid + it * 256;
            int row = ch >> 3, c = ch & 7;
            cp_async16(vb + row * (SVH * 2) + c * 16, vs + (size_t)row * (Tn * 2) + c * 16);
        }
        cp_commit();
    };

    // stage Q (fp16, pre-scaled) + first K/V tile
    {
        const char* qs = (const char*)(Q16 + ((size_t)qt0 * Hn + h) * HDn);
#pragma unroll
        for (int it = 0; it < 8; ++it) {
            int ch = tid + it * 256;
            int row = ch >> 4, c = ch & 15;
            cp_async16(sQ + row * (SKH * 2) + c * 16,
                       qs + (size_t)row * (Hn * HDn * 2) + c * 16);
        }
        cp_commit();
    }
    stageKV(0);

    cp_wait<1>();          // Q done (KV0 may still be in flight)
    __syncthreads();
    uint32_t qf[8][4];
    {
        uint32_t qaddr = sQ + (wid * 16 + frow) * (SKH * 2) + fcol;
#pragma unroll
        for (int ks = 0; ks < 8; ++ks) ldm_x4(qf[ks], qaddr + ks * 32);
    }

    float o[16][4];
#pragma unroll
    for (int i = 0; i < 16; i++)
#pragma unroll
        for (int j = 0; j < 4; j++) o[i][j] = 0.f;
    float mreg[2] = {-1e30f, -1e30f}, lreg[2] = {0.f, 0.f};

    const uint32_t myP = sQ + wid * 16 * (SPH * 2);   // P aliases the Q staging region
    const uint32_t paddr = myP + frow * (SPH * 2) + fcol;

    for (int kt = 0; kt < nkt; ++kt) {
        const int kt0 = kt << 6;
        cp_wait<0>();
        __syncthreads();   // tile kt ready; all warps past previous compute
        if (kt + 1 < nkt) stageKV(kt + 1);

        const uint32_t kaddr = sKb + (kt & 1) * KTB + frow * (SKH * 2) + fcol;
        const uint32_t vaddr = sVb + (kt & 1) * VTB + frow * (SVH * 2) + fcol;

        // ---- S = Q @ K^T ----
        float s[8][4];
#pragma unroll
        for (int i = 0; i < 8; i++)
#pragma unroll
            for (int j = 0; j < 4; j++) s[i][j] = 0.f;
#pragma unroll
        for (int ks = 0; ks < 8; ++ks) {
#pragma unroll
            for (int ntp = 0; ntp < 4; ++ntp) {
                uint32_t bf[4];
                ldm_x4(bf, kaddr + ntp * 16 * (SKH * 2) + ks * 32);
                mma_f16(s[ntp * 2],     qf[ks], bf[0], bf[2]);
                mma_f16(s[ntp * 2 + 1], qf[ks], bf[1], bf[3]);
            }
        }

        if (kt >= nkt - 2) {
            int rowg = qt0 + wid * 16 + r0;
#pragma unroll
            for (int nt = 0; nt < 8; ++nt) {
                int colg = kt0 + nt * 8 + c0;
                if (colg > rowg)          s[nt][0] = -1e30f;
                if (colg + 1 > rowg)      s[nt][1] = -1e30f;
                if (colg > rowg + 8)      s[nt][2] = -1e30f;
                if (colg + 1 > rowg + 8)  s[nt][3] = -1e30f;
            }
        }

        // ---- online softmax ----
#pragma unroll
        for (int hf = 0; hf < 2; ++hf) {
            float rm = -1e30f;
#pragma unroll
            for (int nt = 0; nt < 8; ++nt)
                rm = fmaxf(rm, fmaxf(s[nt][2 * hf], s[nt][2 * hf + 1]));
            rm = fmaxf(rm, __shfl_xor_sync(0xffffffffu, rm, 1));
            rm = fmaxf(rm, __shfl_xor_sync(0xffffffffu, rm, 2));
            float mn = fmaxf(mreg[hf], rm);
            float corr = __expf(mreg[hf] - mn);
            mreg[hf] = mn;
            float su = 0.f;
#pragma unroll
            for (int nt = 0; nt < 8; ++nt) {
                float e0 = __expf(s[nt][2 * hf] - mn);
                float e1 = __expf(s[nt][2 * hf + 1] - mn);
                s[nt][2 * hf] = e0;
                s[nt][2 * hf + 1] = e1;
                su += e0 + e1;
            }
            su += __shfl_xor_sync(0xffffffffu, su, 1);
            su += __shfl_xor_sync(0xffffffffu, su, 2);
            lreg[hf] = lreg[hf] * corr + su;
#pragma unroll
            for (int nt = 0; nt < 16; ++nt) {
                o[nt][2 * hf] *= corr;
                o[nt][2 * hf + 1] *= corr;
            }
        }

        // ---- P (fp16) to warp-private smem ----
#pragma unroll
        for (int nt = 0; nt < 8; ++nt) {
            *(uint32_t*)((char*)smraw + (myP - sQ) + r0 * (SPH * 2) + (nt * 8 + c0) * 2) =
                h2u(__floats2half2_rn(s[nt][0], s[nt][1]));
            *(uint32_t*)((char*)smraw + (myP - sQ) + (r0 + 8) * (SPH * 2) + (nt * 8 + c0) * 2) =
                h2u(__floats2half2_rn(s[nt][2], s[nt][3]));
        }
        __syncwarp();

        // ---- O += P @ V ----
#pragma unroll
        for (int ks = 0; ks < 4; ++ks) {
            uint32_t pf[4];
            ldm_x4(pf, paddr + ks * 32);
#pragma unroll
            for (int np = 0; np < 8; ++np) {
                uint32_t bf[4];
                ldm_x4(bf, vaddr + np * 16 * (SVH * 2) + ks * 32);
                mma_f16(o[2 * np],     pf, bf[0], bf[2]);
                mma_f16(o[2 * np + 1], pf, bf[1], bf[3]);
            }
        }
    }

    float inv0 = 1.0f / lreg[0], inv1 = 1.0f / lreg[1];
    int rowg = qt0 + wid * 16 + r0;
#pragma unroll
    for (int nt = 0; nt < 16; ++nt) {
        size_t base = (size_t)h * HDn + nt * 8 + c0;
        *(__half2*)&AO[(size_t)rowg * (Hn * HDn) + base] =
            __floats2half2_rn(o[nt][0] * inv0, o[nt][1] * inv0);
        *(__half2*)&AO[(size_t)(rowg + 8) * (Hn * HDn) + base] =
            __floats2half2_rn(o[nt][2] * inv1, o[nt][3] * inv1);
    }
}

// ---------------- host orchestration ----------------
extern "C" void kernel_launch(void* const* d_in, const int* in_sizes, int n_in,
                              void* d_out, int out_size) {
    const float* emb = (const float*)d_in[0];
    const float* ln1 = (const float*)d_in[1];
    const float* qw  = (const float*)d_in[2];
    const float* kw  = (const float*)d_in[3];
    const float* vw  = (const float*)d_in[4];
    const float* qn  = (const float*)d_in[5];
    const float* kn  = (const float*)d_in[6];
    const float* ow  = (const float*)d_in[7];
    const float* ln2 = (const float*)d_in[8];
    const float* gw  = (const float*)d_in[9];
    const float* uw  = (const float*)d_in[10];
    const float* dw  = (const float*)d_in[11];
    const float* nw  = (const float*)d_in[12];

    float* out  = (float*)d_out;
    float* keys = out + (size_t)Tn * Dn;
    float* vals = keys + (size_t)Ln * KVn * Tn * HDn;

    float *ph, *pq, *pkt, *pg, *pu;
    __half *pxh, *paoh, *pgh, *pw, *pq16, *pk16, *pvt16;
    cudaGetSymbolAddress((void**)&ph,    g_h);
    cudaGetSymbolAddress((void**)&pq,    g_q);
    cudaGetSymbolAddress((void**)&pkt,   g_kt);
    cudaGetSymbolAddress((void**)&pg,    g_gate);
    cudaGetSymbolAddress((void**)&pu,    g_up);
    cudaGetSymbolAddress((void**)&pxh,   g_xh);
    cudaGetSymbolAddress((void**)&paoh,  g_aoh);
    cudaGetSymbolAddress((void**)&pgh,   g_gh);
    cudaGetSymbolAddress((void**)&pw,    g_w);
    cudaGetSymbolAddress((void**)&pq16,  g_q16);
    cudaGetSymbolAddress((void**)&pk16,  g_k16);
    cudaGetSymbolAddress((void**)&pvt16, g_vt16);

    cudaFuncSetAttribute(attn_h_kernel, cudaFuncAttributeMaxDynamicSharedMemorySize, ATTN_SMEM);
    cudaFuncSetAttribute(hg_qkv_kernel, cudaFuncAttributeMaxDynamicSharedMemorySize, HG_SMEM(128));
    cudaFuncSetAttribute(hg_gu_kernel,  cudaFuncAttributeMaxDynamicSharedMemorySize, HG_SMEM(128));
    cudaFuncSetAttribute(hg_add_kernel, cudaFuncAttributeMaxDynamicSharedMemorySize, HG_SMEM(64));

    {
        Cv7 a;
        size_t offs[7] = { W_Q, W_K, W_V, W_O, W_G, W_U, W_D };
        const float* srcs[7] = { qw, kw, vw, ow, gw, uw, dw };
        size_t ns[7] = {
            (size_t)Ln * Hn * HDn * Dn, (size_t)Ln * KVn * HDn * Dn,
            (size_t)Ln * KVn * HDn * Dn, (size_t)Ln * Dn * Hn * HDn,
            (size_t)Ln * FFn * Dn, (size_t)Ln * FFn * Dn, (size_t)Ln * Dn * FFn };
        int cum = 0;
        for (int i = 0; i < 7; i++) {
            a.s[i] = (const float4*)srcs[i];
            a.d[i] = pw + offs[i];
            a.cum[i] = cum;
            cum += (int)(ns[i] / 4);
        }
        a.cum[7] = cum;
        conv7_kernel<<<(cum + 255) / 256, 256>>>(a);
    }

    cudaMemcpyAsync(ph, emb, sizeof(float) * Tn * Dn, cudaMemcpyDeviceToDevice);
    rope_tables_kernel<<<Tn, 64>>>();

    for (int i = 0; i < Ln; ++i) {
        float* klayer = keys + (size_t)i * KVn * Tn * HDn;
        float* vlayer = vals + (size_t)i * KVn * Tn * HDn;

        rms_rows_kernel<1><<<Tn, 256>>>(ph, ln1 + (size_t)i * Dn, nullptr, pxh);

        hg_qkv_kernel<<<dim3(32, Tn / 128), 256, HG_SMEM(128)>>>(
            pxh,
            pw + W_Q + (size_t)i * (Hn * HDn) * Dn,
            pw + W_K + (size_t)i * (KVn * HDn) * Dn,
            pw + W_V + (size_t)i * (KVn * HDn) * Dn,
            pq, pkt, vlayer, pvt16);

        qknorm_rope_kernel<<<dim3(Tn, Hn + KVn), 128>>>(
            pq, pkt, klayer, pq16, pk16, qn + (size_t)i * HDn, kn + (size_t)i * HDn);

        attn_h_kernel<<<dim3(Tn / 128, Hn), 256, ATTN_SMEM>>>(pq16, pk16, pvt16, paoh);

        hg_add_kernel<<<dim3(Dn / 64, Tn / 128), 256, HG_SMEM(64)>>>(
            paoh, pw + W_O + (size_t)i * Dn * (Hn * HDn), ph, Dn, Hn * HDn);

        rms_rows_kernel<1><<<Tn, 256>>>(ph, ln2 + (size_t)i * Dn, nullptr, pxh);

        hg_gu_kernel<<<dim3(48, Tn / 128), 256, HG_SMEM(128)>>>(
            pxh,
            pw + W_G + (size_t)i * FFn * Dn,
            pw + W_U + (size_t)i * FFn * Dn,
            pg, pu);

        silu_mul_kernel<<<(Tn * FFn / 4 + 255) / 256, 256>>>(
            (const float4*)pg, (const float4*)pu, pgh, Tn * FFn / 4);

        hg_add_kernel<<<dim3(Dn / 64, Tn / 128), 256, HG_SMEM(64)>>>(
            pgh, pw + W_D + (size_t)i * Dn * FFn, ph, Dn, FFn);
    }

    rms_rows_kernel<0><<<Tn, 256>>>(ph, nw, out, nullptr);
}

// round 13
// speedup vs baseline: 1.2744x; 1.0008x over previous
#include <cuda_runtime.h>
#include <cuda_fp16.h>
#include <math.h>
#include <stdint.h>

constexpr int Tn = 2048, Dn = 1024, Hn = 16, KVn = 8, HDn = 128, FFn = 3072, Ln = 5;
constexpr float EPSf = 1e-6f;

// ---------------- scratch ----------------
__device__ float g_h [Tn * Dn];
__device__ float g_cos[Tn * 64];
__device__ float g_sin[Tn * 64];

__device__ __align__(16) __half g_xh  [Tn * Dn];         // rms output
__device__ __align__(16) __half g_aoh [Tn * Hn * HDn];   // attention out
__device__ __align__(16) __half g_q0  [Tn * Hn * HDn];   // pre-rope q
__device__ __align__(16) __half g_k0  [Tn * KVn * HDn];  // pre-rope k
__device__ __align__(16) __half g_gh  [Tn * FFn];        // gate -> silu*u
__device__ __align__(16) __half g_uh  [Tn * FFn];        // up
__device__ __align__(16) __half g_q16 [Tn * Hn * HDn];   // rope'd, pre-scaled q
__device__ __align__(16) __half g_k16 [KVn * Tn * HDn];  // rope'd k
__device__ __align__(16) __half g_vt16[KVn * HDn * Tn];  // V^T [kv][d][t]

constexpr size_t W_Q  = 0;
constexpr size_t W_K  = W_Q + (size_t)Ln * Hn * HDn * Dn;
constexpr size_t W_V  = W_K + (size_t)Ln * KVn * HDn * Dn;
constexpr size_t W_O  = W_V + (size_t)Ln * KVn * HDn * Dn;
constexpr size_t W_G  = W_O + (size_t)Ln * Dn * Hn * HDn;
constexpr size_t W_U  = W_G + (size_t)Ln * FFn * Dn;
constexpr size_t W_D  = W_U + (size_t)Ln * FFn * Dn;
constexpr size_t W_TOT= W_D + (size_t)Ln * Dn * FFn;
__device__ __align__(16) __half g_w[W_TOT];

// ---------------- PTX helpers ----------------
__device__ __forceinline__ uint32_t sptr(const void* p) {
    return (uint32_t)__cvta_generic_to_shared(p);
}
__device__ __forceinline__ void ldm_x4(uint32_t* r, uint32_t addr) {
    asm volatile("ldmatrix.sync.aligned.m8n8.x4.shared.b16 {%0,%1,%2,%3}, [%4];"
                 : "=r"(r[0]), "=r"(r[1]), "=r"(r[2]), "=r"(r[3]) : "r"(addr));
}
__device__ __forceinline__ void mma_f16(float* c, const uint32_t* a, uint32_t b0, uint32_t b1) {
    asm volatile("mma.sync.aligned.m16n8k16.row.col.f32.f16.f16.f32 "
                 "{%0,%1,%2,%3}, {%4,%5,%6,%7}, {%8,%9}, {%0,%1,%2,%3};"
                 : "+f"(c[0]), "+f"(c[1]), "+f"(c[2]), "+f"(c[3])
                 : "r"(a[0]), "r"(a[1]), "r"(a[2]), "r"(a[3]), "r"(b0), "r"(b1));
}
__device__ __forceinline__ void cp_async16(uint32_t dst, const void* src) {
    asm volatile("cp.async.ca.shared.global [%0], [%1], 16;" :: "r"(dst), "l"(src));
}
__device__ __forceinline__ void cp_commit() {
    asm volatile("cp.async.commit_group;" ::: "memory");
}
template <int N>
__device__ __forceinline__ void cp_wait() {
    asm volatile("cp.async.wait_group %0;" :: "n"(N) : "memory");
}
__device__ __forceinline__ uint32_t h2u(__half2 h) { return *(uint32_t*)&h; }

// ---------------- weight fp16 conversion ----------------
struct Cv7 {
    const float4* s[7];
    __half* d[7];
    int cum[8];
};
__global__ void conv7_kernel(Cv7 a) {
    int idx = blockIdx.x * 256 + threadIdx.x;
    if (idx >= a.cum[7]) return;
    int s = 0;
#pragma unroll
    for (int i = 0; i < 6; i++) s += (idx >= a.cum[i + 1]) ? 1 : 0;
    int off = idx - a.cum[s];
    float4 v = a.s[s][off];
    ((uint2*)a.d[s])[off] = make_uint2(h2u(__floats2half2_rn(v.x, v.y)),
                                       h2u(__floats2half2_rn(v.z, v.w)));
}

// ---------------- RoPE tables ----------------
__global__ void rope_tables_kernel() {
    int t = blockIdx.x, j = threadIdx.x;
    float inv = 1.0f / powf(1.0e6f, (float)j * (1.0f / 64.0f));
    g_cos[t * 64 + j] = cosf((float)t * inv);
    g_sin[t * 64 + j] = sinf((float)t * inv);
}

// ---------------- RMSNorm rows ----------------
template <int HALF>
__global__ void rms_rows_kernel(const float* __restrict__ in,
                                const float* __restrict__ w,
                                float* __restrict__ out,
                                __half* __restrict__ oh) {
    int t = blockIdx.x;
    const float4* ip = (const float4*)(in + (size_t)t * Dn);
    const float4* wp = (const float4*)w;
    float4 v = ip[threadIdx.x];
    float s = v.x * v.x + v.y * v.y + v.z * v.z + v.w * v.w;
#pragma unroll
    for (int off = 16; off; off >>= 1) s += __shfl_xor_sync(0xffffffffu, s, off);
    __shared__ float ws[8];
    if ((threadIdx.x & 31) == 0) ws[threadIdx.x >> 5] = s;
    __syncthreads();
    float tot = 0.f;
#pragma unroll
    for (int i = 0; i < 8; i++) tot += ws[i];
    float r = rsqrtf(tot * (1.0f / (float)Dn) + EPSf);
    float4 wv = wp[threadIdx.x];
    float4 o = make_float4(v.x * r * wv.x, v.y * r * wv.y, v.z * r * wv.z, v.w * r * wv.w);
    if (HALF) {
        ((uint2*)(oh + (size_t)t * Dn))[threadIdx.x] =
            make_uint2(h2u(__floats2half2_rn(o.x, o.y)),
                       h2u(__floats2half2_rn(o.z, o.w)));
    } else {
        ((float4*)(out + (size_t)t * Dn))[threadIdx.x] = o;
    }
}

// ---------------- combined Q/K per-head RMSNorm + RoPE (fp16 in) ----------------
__global__ void qknorm_rope_kernel(const __half* __restrict__ q,
                                   const __half* __restrict__ k,
                                   float* __restrict__ ko,
                                   __half* __restrict__ q16,
                                   __half* __restrict__ k16,
                                   const float* __restrict__ qw,
                                   const float* __restrict__ kw) {
    int t = blockIdx.x, h = blockIdx.y, d = threadIdx.x;
    bool isq = h < Hn;
    const __half* row = isq ? (q + ((size_t)t * Hn + h) * HDn)
                            : (k + ((size_t)t * KVn + (h - Hn)) * HDn);
    const float* w = isq ? qw : kw;
    float v = __half2float(row[d]);
    float s = v * v;
#pragma unroll
    for (int off = 16; off; off >>= 1) s += __shfl_xor_sync(0xffffffffu, s, off);
    __shared__ float ws[4];
    if ((d & 31) == 0) ws[d >> 5] = s;
    __syncthreads();
    float r = rsqrtf((ws[0] + ws[1] + ws[2] + ws[3]) * (1.0f / (float)HDn) + EPSf);
    float xn = v * r * w[d];
    __shared__ float sh[128];
    sh[d] = xn;
    __syncthreads();
    float other = (d < 64) ? -sh[d + 64] : sh[d - 64];
    int j = d & 63;
    float o = xn * g_cos[t * 64 + j] + other * g_sin[t * 64 + j];
    if (isq) {
        q16[((size_t)t * Hn + h) * HDn + d] = __float2half(o * 0.0883883476483184f);
    } else {
        size_t idx = ((size_t)(h - Hn) * Tn + t) * HDn + d;
        ko[idx] = o;
        k16[idx] = __float2half(o);
    }
}

// ---------------- silu(g)*u (fp16 in/out, fp32 math) ----------------
__global__ void silu_mul_kernel(const uint2* __restrict__ g, const uint2* __restrict__ u,
                                __half* __restrict__ oh, int n4) {
    int idx = blockIdx.x * blockDim.x + threadIdx.x;
    if (idx < n4) {
        uint2 gv = g[idx], uv = u[idx];
        float2 g0 = __half22float2(*(__half2*)&gv.x), g1 = __half22float2(*(__half2*)&gv.y);
        float2 u0 = __half22float2(*(__half2*)&uv.x), u1 = __half22float2(*(__half2*)&uv.y);
        float r0 = g0.x / (1.0f + __expf(-g0.x)) * u0.x;
        float r1 = g0.y / (1.0f + __expf(-g0.y)) * u0.y;
        float r2 = g1.x / (1.0f + __expf(-g1.x)) * u1.x;
        float r3 = g1.y / (1.0f + __expf(-g1.y)) * u1.y;
        ((uint2*)oh)[idx] = make_uint2(h2u(__floats2half2_rn(r0, r1)),
                                       h2u(__floats2half2_rn(r2, r3)));
    }
}

// ---------------- fp16 tensor-core GEMM NT (2-stage, 2 CTAs/SM, B-skew) ----------------
constexpr int HROWB = 144;
constexpr int ASTB  = 128 * HROWB;
#define HG_SMEM(BN) (2 * (128 + (BN)) * HROWB)

template <int ADD, int BN, int TRANSV, int OUTH>
__device__ __forceinline__ void hgemm_body(const __half* __restrict__ A,
                                           const __half* __restrict__ B,
                                           float* __restrict__ C,
                                           __half* __restrict__ Ch,
                                           __half* __restrict__ Cv,
                                           int N, int K, int m0, int n0,
                                           char* smem) {
    constexpr int BSTB = BN * HROWB;
    constexpr int NT2  = BN / 32;
    const int tid = threadIdx.x, lane = tid & 31, wid = tid >> 5;
    const int wm = wid & 3, wn = wid >> 2;

    const __half* Ag = A + (size_t)m0 * K;
    const __half* Bg = B + (size_t)n0 * K;
    const uint32_t sA = sptr(smem);
    const uint32_t sB = sA + 2 * ASTB;

    float acc[2][BN / 16][4];
#pragma unroll
    for (int i = 0; i < 2; i++)
#pragma unroll
        for (int j = 0; j < BN / 16; j++)
#pragma unroll
            for (int q = 0; q < 4; q++) acc[i][j][q] = 0.f;

    const int frow = ((lane >> 3) & 1) * 8 + (lane & 7);
    const int fcol = (lane >> 4) * 16;
    const int nk = K >> 6;

    auto stage = [&](int st, int kt) {
        const __half* Ak = Ag + (size_t)kt * 64;
        const __half* Bk = Bg + (size_t)kt * 64;
        uint32_t da = sA + st * ASTB;
        uint32_t db = sB + st * BSTB;
#pragma unroll
        for (int it = 0; it < 4; ++it) {
            int ch = tid + it * 256;
            int row = ch >> 3, c16 = ch & 7;
            cp_async16(da + row * HROWB + c16 * 16, Ak + (size_t)row * K + c16 * 8);
        }
#pragma unroll
        for (int it = 0; it < BN / 32; ++it) {
            int ch = tid + it * 256;
            int row = ch >> 3, c16 = ch & 7;
            cp_async16(db + row * HROWB + c16 * 16, Bk + (size_t)row * K + c16 * 8);
        }
        cp_commit();
    };

    stage(0, 0);

    for (int i = 0; i < nk; ++i) {
        cp_wait<0>();
        __syncthreads();
        if (i + 1 < nk) stage((i + 1) & 1, i + 1);

        const int cur = i & 1;
        const uint32_t aaddr = sA + cur * ASTB + (wm * 32 + frow) * HROWB + fcol;
        const uint32_t baddr = sB + cur * BSTB + (wn * (BN / 2) + frow) * HROWB + fcol;
#pragma unroll
        for (int ks = 0; ks < 4; ++ks) {
            uint32_t af[2][4];
            ldm_x4(af[0], aaddr + ks * 32);
            ldm_x4(af[1], aaddr + 16 * HROWB + ks * 32);
            // B-skewed: load B[n2+1] before consuming B[n2]
            uint32_t bf[2][4];
            ldm_x4(bf[0], baddr + ks * 32);
#pragma unroll
            for (int n2 = 0; n2 < NT2; ++n2) {
                const int cb = n2 & 1;
                if (n2 + 1 < NT2)
                    ldm_x4(bf[cb ^ 1], baddr + (n2 + 1) * 16 * HROWB + ks * 32);
#pragma unroll
                for (int mt = 0; mt < 2; ++mt) {
                    mma_f16(acc[mt][n2 * 2],     af[mt], bf[cb][0], bf[cb][2]);
                    mma_f16(acc[mt][n2 * 2 + 1], af[mt], bf[cb][1], bf[cb][3]);
                }
            }
        }
    }

    const int row0 = m0 + wm * 32 + (lane >> 2);
    const int col0 = n0 + wn * (BN / 2) + (lane & 3) * 2;
#pragma unroll
    for (int mt = 0; mt < 2; ++mt)
#pragma unroll
        for (int nt = 0; nt < BN / 16; ++nt) {
            int r = row0 + mt * 16;
            int c = col0 + nt * 8;
            float2 v0 = make_float2(acc[mt][nt][0], acc[mt][nt][1]);
            float2 v1 = make_float2(acc[mt][nt][2], acc[mt][nt][3]);
            if (TRANSV) {
                *(float2*)&C[((size_t)(c >> 7) * Tn + r) * HDn + (c & 127)] = v0;
                *(float2*)&C[((size_t)(c >> 7) * Tn + (r + 8)) * HDn + (c & 127)] = v1;
                size_t vb = ((size_t)(c >> 7) * HDn + (c & 127)) * Tn;
                Cv[vb + r]          = __float2half(v0.x);
                Cv[vb + Tn + r]     = __float2half(v0.y);
                Cv[vb + r + 8]      = __float2half(v1.x);
                Cv[vb + Tn + r + 8] = __float2half(v1.y);
            } else if (OUTH) {
                *(__half2*)&Ch[(size_t)r * N + c]       = __floats2half2_rn(v0.x, v0.y);
                *(__half2*)&Ch[(size_t)(r + 8) * N + c] = __floats2half2_rn(v1.x, v1.y);
            } else {
                float2* p0 = (float2*)&C[(size_t)r * N + c];
                float2* p1 = (float2*)&C[(size_t)(r + 8) * N + c];
                if (ADD) {
                    float2 o0 = *p0, o1 = *p1;
                    v0.x += o0.x; v0.y += o0.y; v1.x += o1.x; v1.y += o1.y;
                }
                *p0 = v0;
                *p1 = v1;
            }
        }
}

__global__ __launch_bounds__(256, 2) void hg_qkv_kernel(
    const __half* __restrict__ xh,
    const __half* __restrict__ wq, const __half* __restrict__ wk, const __half* __restrict__ wv,
    __half* __restrict__ q0, __half* __restrict__ k0,
    float* __restrict__ vlayer, __half* __restrict__ vt16) {
    extern __shared__ char smem[];
    int bx = blockIdx.x, m0 = blockIdx.y * 128;
    if (bx < 16)
        hgemm_body<0, 128, 0, 1>(xh, wq, nullptr, q0, nullptr, Hn * HDn, Dn, m0, bx * 128, smem);
    else if (bx < 24)
        hgemm_body<0, 128, 0, 1>(xh, wk, nullptr, k0, nullptr, KVn * HDn, Dn, m0, (bx - 16) * 128, smem);
    else
        hgemm_body<0, 128, 1, 0>(xh, wv, vlayer, nullptr, vt16, KVn * HDn, Dn, m0, (bx - 24) * 128, smem);
}

__global__ __launch_bounds__(256, 2) void hg_gu_kernel(
    const __half* __restrict__ xh,
    const __half* __restrict__ wg, const __half* __restrict__ wu,
    __half* __restrict__ g, __half* __restrict__ u) {
    extern __shared__ char smem[];
    int bx = blockIdx.x, m0 = blockIdx.y * 128;
    if (bx < 24)
        hgemm_body<0, 128, 0, 1>(xh, wg, nullptr, g, nullptr, FFn, Dn, m0, bx * 128, smem);
    else
        hgemm_body<0, 128, 0, 1>(xh, wu, nullptr, u, nullptr, FFn, Dn, m0, (bx - 24) * 128, smem);
}

__global__ __launch_bounds__(256, 2) void hg_add_kernel(
    const __half* __restrict__ a, const __half* __restrict__ b,
    float* __restrict__ C, int N, int K) {
    extern __shared__ char smem[];
    hgemm_body<1, 64, 0, 0>(a, b, C, nullptr, nullptr, N, K, blockIdx.y * 128, blockIdx.x * 64, smem);
}

// ---------------- fp16 flash attention with cp.async pipelined K/V ----------------
constexpr int SKH = 136, SVH = 72, SPH = 72;
constexpr int KTB = 64 * SKH * 2;
constexpr int VTB = 128 * SVH * 2;
constexpr int QSTB = 128 * SKH * 2;
constexpr int ATTN_SMEM = QSTB + 2 * KTB + 2 * VTB;  // 106496

__global__ __launch_bounds__(256) void attn_h_kernel(const __half* __restrict__ Q16,
                                                     const __half* __restrict__ K16,
                                                     const __half* __restrict__ VT16,
                                                     __half* __restrict__ AO) {
    extern __shared__ char smraw[];
    const uint32_t sQ = sptr(smraw);
    const uint32_t sKb = sQ + QSTB;
    const uint32_t sVb = sKb + 2 * KTB;

    const int h = blockIdx.y;
    const int qt0 = (gridDim.x - 1 - blockIdx.x) * 128;
    const int kv = h >> 1;
    const int tid = threadIdx.x, lane = tid & 31, wid = tid >> 5;
    const int frow = ((lane >> 3) & 1) * 8 + (lane & 7);
    const int fcol = (lane >> 4) * 16;
    const int r0 = lane >> 2, c0 = (lane & 3) * 2;
    const int nkt = (qt0 >> 6) + 2;

    const char* kbase = (const char*)(K16 + (size_t)kv * Tn * HDn);
    const char* vbase = (const char*)(VT16 + (size_t)kv * HDn * Tn);

    auto stageKV = [&](int kt) {
        const int kt0 = kt << 6;
        uint32_t kb = sKb + (kt & 1) * KTB;
        uint32_t vb = sVb + (kt & 1) * VTB;
        const char* ks = kbase + (size_t)kt0 * (HDn * 2);
#pragma unroll
        for (int it = 0; it < 4; ++it) {
            int ch = tid + it * 256;
            int row = ch >> 4, c = ch & 15;
            cp_async16(kb + row * (SKH * 2) + c * 16, ks + (size_t)row * 256 + c * 16);
        }
        const char* vs = vbase + (size_t)kt0 * 2;
#pragma unroll
        for (int it = 0; it < 4; ++it) {
            int ch = tid + it * 256;
            int row = ch >> 3, c = ch & 7;
            cp_async16(vb + row * (SVH * 2) + c * 16, vs + (size_t)row * (Tn * 2) + c * 16);
        }
        cp_commit();
    };

    {
        const char* qs = (const char*)(Q16 + ((size_t)qt0 * Hn + h) * HDn);
#pragma unroll
        for (int it = 0; it < 8; ++it) {
            int ch = tid + it * 256;
            int row = ch >> 4, c = ch & 15;
            cp_async16(sQ + row * (SKH * 2) + c * 16,
                       qs + (size_t)row * (Hn * HDn * 2) + c * 16);
        }
        cp_commit();
    }
    stageKV(0);

    cp_wait<1>();
    __syncthreads();
    uint32_t qf[8][4];
    {
        uint32_t qaddr = sQ + (wid * 16 + frow) * (SKH * 2) + fcol;
#pragma unroll
        for (int ks = 0; ks < 8; ++ks) ldm_x4(qf[ks], qaddr + ks * 32);
    }

    float o[16][4];
#pragma unroll
    for (int i = 0; i < 16; i++)
#pragma unroll
        for (int j = 0; j < 4; j++) o[i][j] = 0.f;
    float mreg[2] = {-1e30f, -1e30f}, lreg[2] = {0.f, 0.f};

    const uint32_t myP = sQ + wid * 16 * (SPH * 2);
    const uint32_t paddr = myP + frow * (SPH * 2) + fcol;

    for (int kt = 0; kt < nkt; ++kt) {
        const int kt0 = kt << 6;
        cp_wait<0>();
        __syncthreads();
        if (kt + 1 < nkt) stageKV(kt + 1);

        const uint32_t kaddr = sKb + (kt & 1) * KTB + frow * (SKH * 2) + fcol;
        const uint32_t vaddr = sVb + (kt & 1) * VTB + frow * (SVH * 2) + fcol;

        float s[8][4];
#pragma unroll
        for (int i = 0; i < 8; i++)
#pragma unroll
            for (int j = 0; j < 4; j++) s[i][j] = 0.f;
#pragma unroll
        for (int ks = 0; ks < 8; ++ks) {
#pragma unroll
            for (int ntp = 0; ntp < 4; ++ntp) {
                uint32_t bf[4];
                ldm_x4(bf, kaddr + ntp * 16 * (SKH * 2) + ks * 32);
                mma_f16(s[ntp * 2],     qf[ks], bf[0], bf[2]);
                mma_f16(s[ntp * 2 + 1], qf[ks], bf[1], bf[3]);
            }
        }

        if (kt >= nkt - 2) {
            int rowg = qt0 + wid * 16 + r0;
#pragma unroll
            for (int nt = 0; nt < 8; ++nt) {
                int colg = kt0 + nt * 8 + c0;
                if (colg > rowg)          s[nt][0] = -1e30f;
                if (colg + 1 > rowg)      s[nt][1] = -1e30f;
                if (colg > rowg + 8)      s[nt][2] = -1e30f;
                if (colg + 1 > rowg + 8)  s[nt][3] = -1e30f;
            }
        }

#pragma unroll
        for (int hf = 0; hf < 2; ++hf) {
            float rm = -1e30f;
#pragma unroll
            for (int nt = 0; nt < 8; ++nt)
                rm = fmaxf(rm, fmaxf(s[nt][2 * hf], s[nt][2 * hf + 1]));
            rm = fmaxf(rm, __shfl_xor_sync(0xffffffffu, rm, 1));
            rm = fmaxf(rm, __shfl_xor_sync(0xffffffffu, rm, 2));
            float mn = fmaxf(mreg[hf], rm);
            float corr = __expf(mreg[hf] - mn);
            mreg[hf] = mn;
            float su = 0.f;
#pragma unroll
            for (int nt = 0; nt < 8; ++nt) {
                float e0 = __expf(s[nt][2 * hf] - mn);
                float e1 = __expf(s[nt][2 * hf + 1] - mn);
                s[nt][2 * hf] = e0;
                s[nt][2 * hf + 1] = e1;
                su += e0 + e1;
            }
            su += __shfl_xor_sync(0xffffffffu, su, 1);
            su += __shfl_xor_sync(0xffffffffu, su, 2);
            lreg[hf] = lreg[hf] * corr + su;
#pragma unroll
            for (int nt = 0; nt < 16; ++nt) {
                o[nt][2 * hf] *= corr;
                o[nt][2 * hf + 1] *= corr;
            }
        }

#pragma unroll
        for (int nt = 0; nt < 8; ++nt) {
            *(uint32_t*)((char*)smraw + (myP - sQ) + r0 * (SPH * 2) + (nt * 8 + c0) * 2) =
                h2u(__floats2half2_rn(s[nt][0], s[nt][1]));
            *(uint32_t*)((char*)smraw + (myP - sQ) + (r0 + 8) * (SPH * 2) + (nt * 8 + c0) * 2) =
                h2u(__floats2half2_rn(s[nt][2], s[nt][3]));
        }
        __syncwarp();

#pragma unroll
        for (int ks = 0; ks < 4; ++ks) {
            uint32_t pf[4];
            ldm_x4(pf, paddr + ks * 32);
#pragma unroll
            for (int np = 0; np < 8; ++np) {
                uint32_t bf[4];
                ldm_x4(bf, vaddr + np * 16 * (SVH * 2) + ks * 32);
                mma_f16(o[2 * np],     pf, bf[0], bf[2]);
                mma_f16(o[2 * np + 1], pf, bf[1], bf[3]);
            }
        }
    }

    float inv0 = 1.0f / lreg[0], inv1 = 1.0f / lreg[1];
    int rowg = qt0 + wid * 16 + r0;
#pragma unroll
    for (int nt = 0; nt < 16; ++nt) {
        size_t base = (size_t)h * HDn + nt * 8 + c0;
        *(__half2*)&AO[(size_t)rowg * (Hn * HDn) + base] =
            __floats2half2_rn(o[nt][0] * inv0, o[nt][1] * inv0);
        *(__half2*)&AO[(size_t)(rowg + 8) * (Hn * HDn) + base] =
            __floats2half2_rn(o[nt][2] * inv1, o[nt][3] * inv1);
    }
}

// ---------------- host orchestration ----------------
extern "C" void kernel_launch(void* const* d_in, const int* in_sizes, int n_in,
                              void* d_out, int out_size) {
    const float* emb = (const float*)d_in[0];
    const float* ln1 = (const float*)d_in[1];
    const float* qw  = (const float*)d_in[2];
    const float* kw  = (const float*)d_in[3];
    const float* vw  = (const float*)d_in[4];
    const float* qn  = (const float*)d_in[5];
    const float* kn  = (const float*)d_in[6];
    const float* ow  = (const float*)d_in[7];
    const float* ln2 = (const float*)d_in[8];
    const float* gw  = (const float*)d_in[9];
    const float* uw  = (const float*)d_in[10];
    const float* dw  = (const float*)d_in[11];
    const float* nw  = (const float*)d_in[12];

    float* out  = (float*)d_out;
    float* keys = out + (size_t)Tn * Dn;
    float* vals = keys + (size_t)Ln * KVn * Tn * HDn;

    float* ph;
    __half *pxh, *paoh, *pq0, *pk0, *pgh, *puh, *pw, *pq16, *pk16, *pvt16;
    cudaGetSymbolAddress((void**)&ph,    g_h);
    cudaGetSymbolAddress((void**)&pxh,   g_xh);
    cudaGetSymbolAddress((void**)&paoh,  g_aoh);
    cudaGetSymbolAddress((void**)&pq0,   g_q0);
    cudaGetSymbolAddress((void**)&pk0,   g_k0);
    cudaGetSymbolAddress((void**)&pgh,   g_gh);
    cudaGetSymbolAddress((void**)&puh,   g_uh);
    cudaGetSymbolAddress((void**)&pw,    g_w);
    cudaGetSymbolAddress((void**)&pq16,  g_q16);
    cudaGetSymbolAddress((void**)&pk16,  g_k16);
    cudaGetSymbolAddress((void**)&pvt16, g_vt16);

    cudaFuncSetAttribute(attn_h_kernel, cudaFuncAttributeMaxDynamicSharedMemorySize, ATTN_SMEM);
    cudaFuncSetAttribute(hg_qkv_kernel, cudaFuncAttributeMaxDynamicSharedMemorySize, HG_SMEM(128));
    cudaFuncSetAttribute(hg_gu_kernel,  cudaFuncAttributeMaxDynamicSharedMemorySize, HG_SMEM(128));
    cudaFuncSetAttribute(hg_add_kernel, cudaFuncAttributeMaxDynamicSharedMemorySize, HG_SMEM(64));

    {
        Cv7 a;
        size_t offs[7] = { W_Q, W_K, W_V, W_O, W_G, W_U, W_D };
        const float* srcs[7] = { qw, kw, vw, ow, gw, uw, dw };
        size_t ns[7] = {
            (size_t)Ln * Hn * HDn * Dn, (size_t)Ln * KVn * HDn * Dn,
            (size_t)Ln * KVn * HDn * Dn, (size_t)Ln * Dn * Hn * HDn,
            (size_t)Ln * FFn * Dn, (size_t)Ln * FFn * Dn, (size_t)Ln * Dn * FFn };
        int cum = 0;
        for (int i = 0; i < 7; i++) {
            a.s[i] = (const float4*)srcs[i];
            a.d[i] = pw + offs[i];
            a.cum[i] = cum;
            cum += (int)(ns[i] / 4);
        }
        a.cum[7] = cum;
        conv7_kernel<<<(cum + 255) / 256, 256>>>(a);
    }

    cudaMemcpyAsync(ph, emb, sizeof(float) * Tn * Dn, cudaMemcpyDeviceToDevice);
    rope_tables_kernel<<<Tn, 64>>>();

    for (int i = 0; i < Ln; ++i) {
        float* klayer = keys + (size_t)i * KVn * Tn * HDn;
        float* vlayer = vals + (size_t)i * KVn * Tn * HDn;

        rms_rows_kernel<1><<<Tn, 256>>>(ph, ln1 + (size_t)i * Dn, nullptr, pxh);

        hg_qkv_kernel<<<dim3(32, Tn / 128), 256, HG_SMEM(128)>>>(
            pxh,
            pw + W_Q + (size_t)i * (Hn * HDn) * Dn,
            pw + W_K + (size_t)i * (KVn * HDn) * Dn,
            pw + W_V + (size_t)i * (KVn * HDn) * Dn,
            pq0, pk0, vlayer, pvt16);

        qknorm_rope_kernel<<<dim3(Tn, Hn + KVn), 128>>>(
            pq0, pk0, klayer, pq16, pk16, qn + (size_t)i * HDn, kn + (size_t)i * HDn);

        attn_h_kernel<<<dim3(Tn / 128, Hn), 256, ATTN_SMEM>>>(pq16, pk16, pvt16, paoh);

        hg_add_kernel<<<dim3(Dn / 64, Tn / 128), 256, HG_SMEM(64)>>>(
            paoh, pw + W_O + (size_t)i * Dn * (Hn * HDn), ph, Dn, Hn * HDn);

        rms_rows_kernel<1><<<Tn, 256>>>(ph, ln2 + (size_t)i * Dn, nullptr, pxh);

        hg_gu_kernel<<<dim3(48, Tn / 128), 256, HG_SMEM(128)>>>(
            pxh,
            pw + W_G + (size_t)i * FFn * Dn,
            pw + W_U + (size_t)i * FFn * Dn,
            pgh, puh);

        silu_mul_kernel<<<(Tn * FFn / 4 + 255) / 256, 256>>>(
            (const uint2*)pgh, (const uint2*)puh, pgh, Tn * FFn / 4);

        hg_add_kernel<<<dim3(Dn / 64, Tn / 128), 256, HG_SMEM(64)>>>(
            pgh, pw + W_D + (size_t)i * Dn * FFn, ph, Dn, FFn);
    }

    rms_rows_kernel<0><<<Tn, 256>>>(ph, nw, out, nullptr);
}

// round 14
// speedup vs baseline: 1.3679x; 1.0733x over previous
#include <cuda_runtime.h>
#include <cuda_fp16.h>
#include <math.h>
#include <stdint.h>

constexpr int Tn = 2048, Dn = 1024, Hn = 16, KVn = 8, HDn = 128, FFn = 3072, Ln = 5;
constexpr float EPSf = 1e-6f;

// ---------------- scratch ----------------
__device__ float g_h [Tn * Dn];
__device__ float g_cos[Tn * 64];
__device__ float g_sin[Tn * 64];

__device__ __align__(16) __half g_xh  [Tn * Dn];
__device__ __align__(16) __half g_aoh [Tn * Hn * HDn];
__device__ __align__(16) __half g_gh  [Tn * FFn];
__device__ __align__(16) __half g_q16 [Tn * Hn * HDn];
__device__ __align__(16) __half g_k16 [KVn * Tn * HDn];
__device__ __align__(16) __half g_vt16[KVn * HDn * Tn];

constexpr size_t W_Q  = 0;
constexpr size_t W_K  = W_Q + (size_t)Ln * Hn * HDn * Dn;
constexpr size_t W_V  = W_K + (size_t)Ln * KVn * HDn * Dn;
constexpr size_t W_O  = W_V + (size_t)Ln * KVn * HDn * Dn;
constexpr size_t W_G  = W_O + (size_t)Ln * Dn * Hn * HDn;
constexpr size_t W_U  = W_G + (size_t)Ln * FFn * Dn;
constexpr size_t W_D  = W_U + (size_t)Ln * FFn * Dn;
constexpr size_t W_TOT= W_D + (size_t)Ln * Dn * FFn;
__device__ __align__(16) __half g_w[W_TOT];

// ---------------- PTX helpers ----------------
__device__ __forceinline__ uint32_t sptr(const void* p) {
    return (uint32_t)__cvta_generic_to_shared(p);
}
__device__ __forceinline__ void ldm_x4(uint32_t* r, uint32_t addr) {
    asm volatile("ldmatrix.sync.aligned.m8n8.x4.shared.b16 {%0,%1,%2,%3}, [%4];"
                 : "=r"(r[0]), "=r"(r[1]), "=r"(r[2]), "=r"(r[3]) : "r"(addr));
}
__device__ __forceinline__ void mma_f16(float* c, const uint32_t* a, uint32_t b0, uint32_t b1) {
    asm volatile("mma.sync.aligned.m16n8k16.row.col.f32.f16.f16.f32 "
                 "{%0,%1,%2,%3}, {%4,%5,%6,%7}, {%8,%9}, {%0,%1,%2,%3};"
                 : "+f"(c[0]), "+f"(c[1]), "+f"(c[2]), "+f"(c[3])
                 : "r"(a[0]), "r"(a[1]), "r"(a[2]), "r"(a[3]), "r"(b0), "r"(b1));
}
__device__ __forceinline__ void cp_async16(uint32_t dst, const void* src) {
    asm volatile("cp.async.ca.shared.global [%0], [%1], 16;" :: "r"(dst), "l"(src));
}
__device__ __forceinline__ void cp_commit() {
    asm volatile("cp.async.commit_group;" ::: "memory");
}
template <int N>
__device__ __forceinline__ void cp_wait() {
    asm volatile("cp.async.wait_group %0;" :: "n"(N) : "memory");
}
__device__ __forceinline__ uint32_t h2u(__half2 h) { return *(uint32_t*)&h; }

// ---------------- weight fp16 conversion ----------------
struct Cv7 {
    const float4* s[7];
    __half* d[7];
    int cum[8];
};
__global__ void conv7_kernel(Cv7 a) {
    int idx = blockIdx.x * 256 + threadIdx.x;
    if (idx >= a.cum[7]) return;
    int s = 0;
#pragma unroll
    for (int i = 0; i < 6; i++) s += (idx >= a.cum[i + 1]) ? 1 : 0;
    int off = idx - a.cum[s];
    float4 v = a.s[s][off];
    ((uint2*)a.d[s])[off] = make_uint2(h2u(__floats2half2_rn(v.x, v.y)),
                                       h2u(__floats2half2_rn(v.z, v.w)));
}

// ---------------- RoPE tables ----------------
__global__ void rope_tables_kernel() {
    int t = blockIdx.x, j = threadIdx.x;
    float inv = 1.0f / powf(1.0e6f, (float)j * (1.0f / 64.0f));
    g_cos[t * 64 + j] = cosf((float)t * inv);
    g_sin[t * 64 + j] = sinf((float)t * inv);
}

// ---------------- RMSNorm rows ----------------
template <int HALF>
__global__ void rms_rows_kernel(const float* __restrict__ in,
                                const float* __restrict__ w,
                                float* __restrict__ out,
                                __half* __restrict__ oh) {
    int t = blockIdx.x;
    const float4* ip = (const float4*)(in + (size_t)t * Dn);
    const float4* wp = (const float4*)w;
    float4 v = ip[threadIdx.x];
    float s = v.x * v.x + v.y * v.y + v.z * v.z + v.w * v.w;
#pragma unroll
    for (int off = 16; off; off >>= 1) s += __shfl_xor_sync(0xffffffffu, s, off);
    __shared__ float ws[8];
    if ((threadIdx.x & 31) == 0) ws[threadIdx.x >> 5] = s;
    __syncthreads();
    float tot = 0.f;
#pragma unroll
    for (int i = 0; i < 8; i++) tot += ws[i];
    float r = rsqrtf(tot * (1.0f / (float)Dn) + EPSf);
    float4 wv = wp[threadIdx.x];
    float4 o = make_float4(v.x * r * wv.x, v.y * r * wv.y, v.z * r * wv.z, v.w * r * wv.w);
    if (HALF) {
        ((uint2*)(oh + (size_t)t * Dn))[threadIdx.x] =
            make_uint2(h2u(__floats2half2_rn(o.x, o.y)),
                       h2u(__floats2half2_rn(o.z, o.w)));
    } else {
        ((float4*)(out + (size_t)t * Dn))[threadIdx.x] = o;
    }
}

// ---------------- fp16 tensor-core GEMM NT (2-stage) with fused epilogues ----------------
// EPI: 0 = fp32 +=ADD, 1 = (unused), 2 = V (fp32 vals + fp16 V^T), 3 = Q norm+rope, 4 = K norm+rope
constexpr int HROWB = 144;
constexpr int ASTB  = 128 * HROWB;
#define HG_SMEM(BN) (2 * (128 + (BN)) * HROWB)

template <int ADD, int BN, int EPI>
__device__ __forceinline__ void hgemm_body(const __half* __restrict__ A,
                                           const __half* __restrict__ B,
                                           float* __restrict__ C,
                                           __half* __restrict__ Ch,
                                           const float* __restrict__ wnorm,
                                           int N, int K, int m0, int n0,
                                           char* smem) {
    constexpr int BSTB = BN * HROWB;
    constexpr int NT2  = BN / 32;
    const int tid = threadIdx.x, lane = tid & 31, wid = tid >> 5;
    const int wm = wid & 3, wn = wid >> 2;

    const __half* Ag = A + (size_t)m0 * K;
    const __half* Bg = B + (size_t)n0 * K;
    const uint32_t sA = sptr(smem);
    const uint32_t sB = sA + 2 * ASTB;

    float acc[2][BN / 16][4];
#pragma unroll
    for (int i = 0; i < 2; i++)
#pragma unroll
        for (int j = 0; j < BN / 16; j++)
#pragma unroll
            for (int q = 0; q < 4; q++) acc[i][j][q] = 0.f;

    const int frow = ((lane >> 3) & 1) * 8 + (lane & 7);
    const int fcol = (lane >> 4) * 16;
    const int nk = K >> 6;

    auto stage = [&](int st, int kt) {
        const __half* Ak = Ag + (size_t)kt * 64;
        const __half* Bk = Bg + (size_t)kt * 64;
        uint32_t da = sA + st * ASTB;
        uint32_t db = sB + st * BSTB;
#pragma unroll
        for (int it = 0; it < 4; ++it) {
            int ch = tid + it * 256;
            int row = ch >> 3, c16 = ch & 7;
            cp_async16(da + row * HROWB + c16 * 16, Ak + (size_t)row * K + c16 * 8);
        }
#pragma unroll
        for (int it = 0; it < BN / 32; ++it) {
            int ch = tid + it * 256;
            int row = ch >> 3, c16 = ch & 7;
            cp_async16(db + row * HROWB + c16 * 16, Bk + (size_t)row * K + c16 * 8);
        }
        cp_commit();
    };

    stage(0, 0);

    for (int i = 0; i < nk; ++i) {
        cp_wait<0>();
        __syncthreads();
        if (i + 1 < nk) stage((i + 1) & 1, i + 1);

        const int cur = i & 1;
        const uint32_t aaddr = sA + cur * ASTB + (wm * 32 + frow) * HROWB + fcol;
        const uint32_t baddr = sB + cur * BSTB + (wn * (BN / 2) + frow) * HROWB + fcol;
#pragma unroll
        for (int ks = 0; ks < 4; ++ks) {
            uint32_t af[2][4];
            ldm_x4(af[0], aaddr + ks * 32);
            ldm_x4(af[1], aaddr + 16 * HROWB + ks * 32);
#pragma unroll
            for (int n2 = 0; n2 < NT2; ++n2) {
                uint32_t bf[4];
                ldm_x4(bf, baddr + n2 * 16 * HROWB + ks * 32);
#pragma unroll
                for (int mt = 0; mt < 2; ++mt) {
                    mma_f16(acc[mt][n2 * 2],     af[mt], bf[0], bf[2]);
                    mma_f16(acc[mt][n2 * 2 + 1], af[mt], bf[1], bf[3]);
                }
            }
        }
    }

    const int row0 = m0 + wm * 32 + (lane >> 2);
    const int col0 = n0 + wn * (BN / 2) + (lane & 3) * 2;

    if (EPI == 3 || EPI == 4) {
        // ---- fused per-head RMSNorm + RoPE (BN == 128; one head per CTA) ----
        __syncthreads();              // all frag reads done; smem reusable
        float* sE = (float*)smem;     // [128][132] fp32
        const int lr = wm * 32 + (lane >> 2);
        const int lc = wn * 64 + (lane & 3) * 2;
#pragma unroll
        for (int mt = 0; mt < 2; ++mt)
#pragma unroll
            for (int nt = 0; nt < BN / 16; ++nt) {
                int r = lr + mt * 16, c = lc + nt * 8;
                *(float2*)&sE[r * 132 + c] = make_float2(acc[mt][nt][0], acc[mt][nt][1]);
                *(float2*)&sE[(r + 8) * 132 + c] = make_float2(acc[mt][nt][2], acc[mt][nt][3]);
            }
        __syncthreads();

        const int head = n0 >> 7;
        const int d0 = lane * 4;
        const int dd = (d0 < 64) ? d0 + 64 : d0 - 64;
        const float sgn = (d0 < 64) ? -1.f : 1.f;
        const float w0 = wnorm[d0], w1 = wnorm[d0 + 1], w2 = wnorm[d0 + 2], w3 = wnorm[d0 + 3];
        const float wo0 = wnorm[dd], wo1 = wnorm[dd + 1], wo2 = wnorm[dd + 2], wo3 = wnorm[dd + 3];
        const int j0 = d0 & 63;

        for (int it = 0; it < 16; ++it) {
            int row = wid * 16 + it;
            int t = m0 + row;
            float4 v  = *(float4*)&sE[row * 132 + d0];
            float4 vo = *(float4*)&sE[row * 132 + dd];
            float ss = v.x * v.x + v.y * v.y + v.z * v.z + v.w * v.w;
#pragma unroll
            for (int o = 16; o; o >>= 1) ss += __shfl_xor_sync(0xffffffffu, ss, o);
            float rr = rsqrtf(ss * (1.0f / 128.f) + EPSf);
            float c0 = g_cos[t * 64 + j0],     s0 = g_sin[t * 64 + j0];
            float c1 = g_cos[t * 64 + j0 + 1], s1 = g_sin[t * 64 + j0 + 1];
            float c2 = g_cos[t * 64 + j0 + 2], s2 = g_sin[t * 64 + j0 + 2];
            float c3 = g_cos[t * 64 + j0 + 3], s3 = g_sin[t * 64 + j0 + 3];
            float o0 = v.x * rr * w0 * c0 + sgn * vo.x * rr * wo0 * s0;
            float o1 = v.y * rr * w1 * c1 + sgn * vo.y * rr * wo1 * s1;
            float o2 = v.z * rr * w2 * c2 + sgn * vo.z * rr * wo2 * s2;
            float o3 = v.w * rr * w3 * c3 + sgn * vo.w * rr * wo3 * s3;
            if (EPI == 3) {
                constexpr float sc = 0.0883883476483184f;
                uint2 p = make_uint2(h2u(__floats2half2_rn(o0 * sc, o1 * sc)),
                                     h2u(__floats2half2_rn(o2 * sc, o3 * sc)));
                *(uint2*)&Ch[((size_t)t * Hn + head) * HDn + d0] = p;
            } else {
                size_t idx = ((size_t)head * Tn + t) * HDn + d0;
                *(float4*)&C[idx] = make_float4(o0, o1, o2, o3);
                *(uint2*)&Ch[idx] = make_uint2(h2u(__floats2half2_rn(o0, o1)),
                                               h2u(__floats2half2_rn(o2, o3)));
            }
        }
        return;
    }

#pragma unroll
    for (int mt = 0; mt < 2; ++mt)
#pragma unroll
        for (int nt = 0; nt < BN / 16; ++nt) {
            int r = row0 + mt * 16;
            int c = col0 + nt * 8;
            float2 v0 = make_float2(acc[mt][nt][0], acc[mt][nt][1]);
            float2 v1 = make_float2(acc[mt][nt][2], acc[mt][nt][3]);
            if (EPI == 2) {
                *(float2*)&C[((size_t)(c >> 7) * Tn + r) * HDn + (c & 127)] = v0;
                *(float2*)&C[((size_t)(c >> 7) * Tn + (r + 8)) * HDn + (c & 127)] = v1;
                size_t vb = ((size_t)(c >> 7) * HDn + (c & 127)) * Tn;
                Ch[vb + r]          = __float2half(v0.x);
                Ch[vb + Tn + r]     = __float2half(v0.y);
                Ch[vb + r + 8]      = __float2half(v1.x);
                Ch[vb + Tn + r + 8] = __float2half(v1.y);
            } else {
                float2* p0 = (float2*)&C[(size_t)r * N + c];
                float2* p1 = (float2*)&C[(size_t)(r + 8) * N + c];
                if (ADD) {
                    float2 o0 = *p0, o1 = *p1;
                    v0.x += o0.x; v0.y += o0.y; v1.x += o1.x; v1.y += o1.y;
                }
                *p0 = v0;
                *p1 = v1;
            }
        }
}

// fused QKV + norm/rope: grid.x = 16 (q) + 8 (k) + 8 (v)
__global__ __launch_bounds__(256, 2) void hg_qkv_kernel(
    const __half* __restrict__ xh,
    const __half* __restrict__ wq, const __half* __restrict__ wk, const __half* __restrict__ wv,
    const float* __restrict__ qn, const float* __restrict__ kn,
    __half* __restrict__ q16, float* __restrict__ klayer, __half* __restrict__ k16,
    float* __restrict__ vlayer, __half* __restrict__ vt16) {
    extern __shared__ char smem[];
    int bx = blockIdx.x, m0 = blockIdx.y * 128;
    if (bx < 16)
        hgemm_body<0, 128, 3>(xh, wq, nullptr, q16, qn, Hn * HDn, Dn, m0, bx * 128, smem);
    else if (bx < 24)
        hgemm_body<0, 128, 4>(xh, wk, klayer, k16, kn, KVn * HDn, Dn, m0, (bx - 16) * 128, smem);
    else
        hgemm_body<0, 128, 2>(xh, wv, vlayer, vt16, nullptr, KVn * HDn, Dn, m0, (bx - 24) * 128, smem);
}

// gate+up in one CTA with fused silu(g)*u epilogue; grid (FFn/64, Tn/128)
__global__ __launch_bounds__(256, 2) void hg_gusilu_kernel(
    const __half* __restrict__ xh,
    const __half* __restrict__ wg, const __half* __restrict__ wu,
    __half* __restrict__ out) {
    extern __shared__ char smem[];
    const int m0 = blockIdx.y * 128, n0 = blockIdx.x * 64;
    const int tid = threadIdx.x, lane = tid & 31, wid = tid >> 5;
    const int wm = wid & 3, wn = wid >> 2;

    const __half* Ag = xh + (size_t)m0 * Dn;
    const __half* Gg = wg + (size_t)n0 * Dn;
    const __half* Ug = wu + (size_t)n0 * Dn;
    const uint32_t sA = sptr(smem);
    const uint32_t sB = sA + 2 * ASTB;      // stage: rows 0-63 g, 64-127 u
    constexpr int BSTB = 128 * HROWB;

    float ag[2][4][4], au[2][4][4];
#pragma unroll
    for (int i = 0; i < 2; i++)
#pragma unroll
        for (int j = 0; j < 4; j++)
#pragma unroll
            for (int q = 0; q < 4; q++) { ag[i][j][q] = 0.f; au[i][j][q] = 0.f; }

    const int frow = ((lane >> 3) & 1) * 8 + (lane & 7);
    const int fcol = (lane >> 4) * 16;
    const int nk = Dn >> 6;

    auto stage = [&](int st, int kt) {
        const __half* Ak = Ag + (size_t)kt * 64;
        const __half* Gk = Gg + (size_t)kt * 64;
        const __half* Uk = Ug + (size_t)kt * 64;
        uint32_t da = sA + st * ASTB;
        uint32_t db = sB + st * BSTB;
#pragma unroll
        for (int it = 0; it < 4; ++it) {
            int ch = tid + it * 256;
            int row = ch >> 3, c16 = ch & 7;
            cp_async16(da + row * HROWB + c16 * 16, Ak + (size_t)row * Dn + c16 * 8);
        }
#pragma unroll
        for (int it = 0; it < 2; ++it) {
            int ch = tid + it * 256;
            int row = ch >> 3, c16 = ch & 7;
            cp_async16(db + row * HROWB + c16 * 16, Gk + (size_t)row * Dn + c16 * 8);
            cp_async16(db + (64 + row) * HROWB + c16 * 16, Uk + (size_t)row * Dn + c16 * 8);
        }
        cp_commit();
    };

    stage(0, 0);

    for (int i = 0; i < nk; ++i) {
        cp_wait<0>();
        __syncthreads();
        if (i + 1 < nk) stage((i + 1) & 1, i + 1);

        const int cur = i & 1;
        const uint32_t aaddr = sA + cur * ASTB + (wm * 32 + frow) * HROWB + fcol;
        const uint32_t gaddr = sB + cur * BSTB + (wn * 32 + frow) * HROWB + fcol;
        const uint32_t uaddr = gaddr + 64 * HROWB;
#pragma unroll
        for (int ks = 0; ks < 4; ++ks) {
            uint32_t af[2][4];
            ldm_x4(af[0], aaddr + ks * 32);
            ldm_x4(af[1], aaddr + 16 * HROWB + ks * 32);
#pragma unroll
            for (int n2 = 0; n2 < 2; ++n2) {
                uint32_t bg[4], bu[4];
                ldm_x4(bg, gaddr + n2 * 16 * HROWB + ks * 32);
                ldm_x4(bu, uaddr + n2 * 16 * HROWB + ks * 32);
#pragma unroll
                for (int mt = 0; mt < 2; ++mt) {
                    mma_f16(ag[mt][n2 * 2],     af[mt], bg[0], bg[2]);
                    mma_f16(ag[mt][n2 * 2 + 1], af[mt], bg[1], bg[3]);
                    mma_f16(au[mt][n2 * 2],     af[mt], bu[0], bu[2]);
                    mma_f16(au[mt][n2 * 2 + 1], af[mt], bu[1], bu[3]);
                }
            }
        }
    }

    const int row0 = m0 + wm * 32 + (lane >> 2);
    const int col0 = n0 + wn * 32 + (lane & 3) * 2;
#pragma unroll
    for (int mt = 0; mt < 2; ++mt)
#pragma unroll
        for (int nt = 0; nt < 4; ++nt) {
            int r = row0 + mt * 16;
            int c = col0 + nt * 8;
            float g0 = ag[mt][nt][0], g1 = ag[mt][nt][1];
            float g2 = ag[mt][nt][2], g3 = ag[mt][nt][3];
            float r0 = g0 / (1.0f + __expf(-g0)) * au[mt][nt][0];
            float r1 = g1 / (1.0f + __expf(-g1)) * au[mt][nt][1];
            float r2 = g2 / (1.0f + __expf(-g2)) * au[mt][nt][2];
            float r3 = g3 / (1.0f + __expf(-g3)) * au[mt][nt][3];
            *(__half2*)&out[(size_t)r * FFn + c]       = __floats2half2_rn(r0, r1);
            *(__half2*)&out[(size_t)(r + 8) * FFn + c] = __floats2half2_rn(r2, r3);
        }
}

__global__ __launch_bounds__(256, 2) void hg_add_kernel(
    const __half* __restrict__ a, const __half* __restrict__ b,
    float* __restrict__ C, int N, int K) {
    extern __shared__ char smem[];
    hgemm_body<1, 64, 0>(a, b, C, nullptr, nullptr, N, K, blockIdx.y * 128, blockIdx.x * 64, smem);
}

// ---------------- fp16 flash attention with cp.async pipelined K/V ----------------
constexpr int SKH = 136, SVH = 72, SPH = 72;
constexpr int KTB = 64 * SKH * 2;
constexpr int VTB = 128 * SVH * 2;
constexpr int QSTB = 128 * SKH * 2;
constexpr int ATTN_SMEM = QSTB + 2 * KTB + 2 * VTB;  // 106496

__global__ __launch_bounds__(256) void attn_h_kernel(const __half* __restrict__ Q16,
                                                     const __half* __restrict__ K16,
                                                     const __half* __restrict__ VT16,
                                                     __half* __restrict__ AO) {
    extern __shared__ char smraw[];
    const uint32_t sQ = sptr(smraw);
    const uint32_t sKb = sQ + QSTB;
    const uint32_t sVb = sKb + 2 * KTB;

    const int h = blockIdx.y;
    const int qt0 = (gridDim.x - 1 - blockIdx.x) * 128;
    const int kv = h >> 1;
    const int tid = threadIdx.x, lane = tid & 31, wid = tid >> 5;
    const int frow = ((lane >> 3) & 1) * 8 + (lane & 7);
    const int fcol = (lane >> 4) * 16;
    const int r0 = lane >> 2, c0 = (lane & 3) * 2;
    const int nkt = (qt0 >> 6) + 2;

    const char* kbase = (const char*)(K16 + (size_t)kv * Tn * HDn);
    const char* vbase = (const char*)(VT16 + (size_t)kv * HDn * Tn);

    auto stageKV = [&](int kt) {
        const int kt0 = kt << 6;
        uint32_t kb = sKb + (kt & 1) * KTB;
        uint32_t vb = sVb + (kt & 1) * VTB;
        const char* ks = kbase + (size_t)kt0 * (HDn * 2);
#pragma unroll
        for (int it = 0; it < 4; ++it) {
            int ch = tid + it * 256;
            int row = ch >> 4, c = ch & 15;
            cp_async16(kb + row * (SKH * 2) + c * 16, ks + (size_t)row * 256 + c * 16);
        }
        const char* vs = vbase + (size_t)kt0 * 2;
#pragma unroll
        for (int it = 0; it < 4; ++it) {
            int ch = tid + it * 256;
            int row = ch >> 3, c = ch & 7;
            cp_async16(vb + row * (SVH * 2) + c * 16, vs + (size_t)row * (Tn * 2) + c * 16);
        }
        cp_commit();
    };

    {
        const char* qs = (const char*)(Q16 + ((size_t)qt0 * Hn + h) * HDn);
#pragma unroll
        for (int it = 0; it < 8; ++it) {
            int ch = tid + it * 256;
            int row = ch >> 4, c = ch & 15;
            cp_async16(sQ + row * (SKH * 2) + c * 16,
                       qs + (size_t)row * (Hn * HDn * 2) + c * 16);
        }
        cp_commit();
    }
    stageKV(0);

    cp_wait<1>();
    __syncthreads();
    uint32_t qf[8][4];
    {
        uint32_t qaddr = sQ + (wid * 16 + frow) * (SKH * 2) + fcol;
#pragma unroll
        for (int ks = 0; ks < 8; ++ks) ldm_x4(qf[ks], qaddr + ks * 32);
    }

    float o[16][4];
#pragma unroll
    for (int i = 0; i < 16; i++)
#pragma unroll
        for (int j = 0; j < 4; j++) o[i][j] = 0.f;
    float mreg[2] = {-1e30f, -1e30f}, lreg[2] = {0.f, 0.f};

    const uint32_t myP = sQ + wid * 16 * (SPH * 2);
    const uint32_t paddr = myP + frow * (SPH * 2) + fcol;

    for (int kt = 0; kt < nkt; ++kt) {
        const int kt0 = kt << 6;
        cp_wait<0>();
        __syncthreads();
        if (kt + 1 < nkt) stageKV(kt + 1);

        const uint32_t kaddr = sKb + (kt & 1) * KTB + frow * (SKH * 2) + fcol;
        const uint32_t vaddr = sVb + (kt & 1) * VTB + frow * (SVH * 2) + fcol;

        float s[8][4];
#pragma unroll
        for (int i = 0; i < 8; i++)
#pragma unroll
            for (int j = 0; j < 4; j++) s[i][j] = 0.f;
#pragma unroll
        for (int ks = 0; ks < 8; ++ks) {
#pragma unroll
            for (int ntp = 0; ntp < 4; ++ntp) {
                uint32_t bf[4];
                ldm_x4(bf, kaddr + ntp * 16 * (SKH * 2) + ks * 32);
                mma_f16(s[ntp * 2],     qf[ks], bf[0], bf[2]);
                mma_f16(s[ntp * 2 + 1], qf[ks], bf[1], bf[3]);
            }
        }

        if (kt >= nkt - 2) {
            int rowg = qt0 + wid * 16 + r0;
#pragma unroll
            for (int nt = 0; nt < 8; ++nt) {
                int colg = kt0 + nt * 8 + c0;
                if (colg > rowg)          s[nt][0] = -1e30f;
                if (colg + 1 > rowg)      s[nt][1] = -1e30f;
                if (colg > rowg + 8)      s[nt][2] = -1e30f;
                if (colg + 1 > rowg + 8)  s[nt][3] = -1e30f;
            }
        }

#pragma unroll
        for (int hf = 0; hf < 2; ++hf) {
            float rm = -1e30f;
#pragma unroll
            for (int nt = 0; nt < 8; ++nt)
                rm = fmaxf(rm, fmaxf(s[nt][2 * hf], s[nt][2 * hf + 1]));
            rm = fmaxf(rm, __shfl_xor_sync(0xffffffffu, rm, 1));
            rm = fmaxf(rm, __shfl_xor_sync(0xffffffffu, rm, 2));
            float mn = fmaxf(mreg[hf], rm);
            float corr = __expf(mreg[hf] - mn);
            mreg[hf] = mn;
            float su = 0.f;
#pragma unroll
            for (int nt = 0; nt < 8; ++nt) {
                float e0 = __expf(s[nt][2 * hf] - mn);
                float e1 = __expf(s[nt][2 * hf + 1] - mn);
                s[nt][2 * hf] = e0;
                s[nt][2 * hf + 1] = e1;
                su += e0 + e1;
            }
            su += __shfl_xor_sync(0xffffffffu, su, 1);
            su += __shfl_xor_sync(0xffffffffu, su, 2);
            lreg[hf] = lreg[hf] * corr + su;
#pragma unroll
            for (int nt = 0; nt < 16; ++nt) {
                o[nt][2 * hf] *= corr;
                o[nt][2 * hf + 1] *= corr;
            }
        }

#pragma unroll
        for (int nt = 0; nt < 8; ++nt) {
            *(uint32_t*)((char*)smraw + (myP - sQ) + r0 * (SPH * 2) + (nt * 8 + c0) * 2) =
                h2u(__floats2half2_rn(s[nt][0], s[nt][1]));
            *(uint32_t*)((char*)smraw + (myP - sQ) + (r0 + 8) * (SPH * 2) + (nt * 8 + c0) * 2) =
                h2u(__floats2half2_rn(s[nt][2], s[nt][3]));
        }
        __syncwarp();

#pragma unroll
        for (int ks = 0; ks < 4; ++ks) {
            uint32_t pf[4];
            ldm_x4(pf, paddr + ks * 32);
#pragma unroll
            for (int np = 0; np < 8; ++np) {
                uint32_t bf[4];
                ldm_x4(bf, vaddr + np * 16 * (SVH * 2) + ks * 32);
                mma_f16(o[2 * np],     pf, bf[0], bf[2]);
                mma_f16(o[2 * np + 1], pf, bf[1], bf[3]);
            }
        }
    }

    float inv0 = 1.0f / lreg[0], inv1 = 1.0f / lreg[1];
    int rowg = qt0 + wid * 16 + r0;
#pragma unroll
    for (int nt = 0; nt < 16; ++nt) {
        size_t base = (size_t)h * HDn + nt * 8 + c0;
        *(__half2*)&AO[(size_t)rowg * (Hn * HDn) + base] =
            __floats2half2_rn(o[nt][0] * inv0, o[nt][1] * inv0);
        *(__half2*)&AO[(size_t)(rowg + 8) * (Hn * HDn) + base] =
            __floats2half2_rn(o[nt][2] * inv1, o[nt][3] * inv1);
    }
}

// ---------------- host orchestration ----------------
extern "C" void kernel_launch(void* const* d_in, const int* in_sizes, int n_in,
                              void* d_out, int out_size) {
    const float* emb = (const float*)d_in[0];
    const float* ln1 = (const float*)d_in[1];
    const float* qw  = (const float*)d_in[2];
    const float* kw  = (const float*)d_in[3];
    const float* vw  = (const float*)d_in[4];
    const float* qn  = (const float*)d_in[5];
    const float* kn  = (const float*)d_in[6];
    const float* ow  = (const float*)d_in[7];
    const float* ln2 = (const float*)d_in[8];
    const float* gw  = (const float*)d_in[9];
    const float* uw  = (const float*)d_in[10];
    const float* dw  = (const float*)d_in[11];
    const float* nw  = (const float*)d_in[12];

    float* out  = (float*)d_out;
    float* keys = out + (size_t)Tn * Dn;
    float* vals = keys + (size_t)Ln * KVn * Tn * HDn;

    float* ph;
    __half *pxh, *paoh, *pgh, *pw, *pq16, *pk16, *pvt16;
    cudaGetSymbolAddress((void**)&ph,    g_h);
    cudaGetSymbolAddress((void**)&pxh,   g_xh);
    cudaGetSymbolAddress((void**)&paoh,  g_aoh);
    cudaGetSymbolAddress((void**)&pgh,   g_gh);
    cudaGetSymbolAddress((void**)&pw,    g_w);
    cudaGetSymbolAddress((void**)&pq16,  g_q16);
    cudaGetSymbolAddress((void**)&pk16,  g_k16);
    cudaGetSymbolAddress((void**)&pvt16, g_vt16);

    cudaFuncSetAttribute(attn_h_kernel, cudaFuncAttributeMaxDynamicSharedMemorySize, ATTN_SMEM);
    cudaFuncSetAttribute(hg_qkv_kernel, cudaFuncAttributeMaxDynamicSharedMemorySize, HG_SMEM(128));
    cudaFuncSetAttribute(hg_gusilu_kernel, cudaFuncAttributeMaxDynamicSharedMemorySize, HG_SMEM(128));
    cudaFuncSetAttribute(hg_add_kernel, cudaFuncAttributeMaxDynamicSharedMemorySize, HG_SMEM(64));

    {
        Cv7 a;
        size_t offs[7] = { W_Q, W_K, W_V, W_O, W_G, W_U, W_D };
        const float* srcs[7] = { qw, kw, vw, ow, gw, uw, dw };
        size_t ns[7] = {
            (size_t)Ln * Hn * HDn * Dn, (size_t)Ln * KVn * HDn * Dn,
            (size_t)Ln * KVn * HDn * Dn, (size_t)Ln * Dn * Hn * HDn,
            (size_t)Ln * FFn * Dn, (size_t)Ln * FFn * Dn, (size_t)Ln * Dn * FFn };
        int cum = 0;
        for (int i = 0; i < 7; i++) {
            a.s[i] = (const float4*)srcs[i];
            a.d[i] = pw + offs[i];
            a.cum[i] = cum;
            cum += (int)(ns[i] / 4);
        }
        a.cum[7] = cum;
        conv7_kernel<<<(cum + 255) / 256, 256>>>(a);
    }

    cudaMemcpyAsync(ph, emb, sizeof(float) * Tn * Dn, cudaMemcpyDeviceToDevice);
    rope_tables_kernel<<<Tn, 64>>>();

    for (int i = 0; i < Ln; ++i) {
        float* klayer = keys + (size_t)i * KVn * Tn * HDn;
        float* vlayer = vals + (size_t)i * KVn * Tn * HDn;

        rms_rows_kernel<1><<<Tn, 256>>>(ph, ln1 + (size_t)i * Dn, nullptr, pxh);

        hg_qkv_kernel<<<dim3(32, Tn / 128), 256, HG_SMEM(128)>>>(
            pxh,
            pw + W_Q + (size_t)i * (Hn * HDn) * Dn,
            pw + W_K + (size_t)i * (KVn * HDn) * Dn,
            pw + W_V + (size_t)i * (KVn * HDn) * Dn,
            qn + (size_t)i * HDn, kn + (size_t)i * HDn,
            pq16, klayer, pk16, vlayer, pvt16);

        attn_h_kernel<<<dim3(Tn / 128, Hn), 256, ATTN_SMEM>>>(pq16, pk16, pvt16, paoh);

        hg_add_kernel<<<dim3(Dn / 64, Tn / 128), 256, HG_SMEM(64)>>>(
            paoh, pw + W_O + (size_t)i * Dn * (Hn * HDn), ph, Dn, Hn * HDn);

        rms_rows_kernel<1><<<Tn, 256>>>(ph, ln2 + (size_t)i * Dn, nullptr, pxh);

        hg_gusilu_kernel<<<dim3(FFn / 64, Tn / 128), 256, HG_SMEM(128)>>>(
            pxh,
            pw + W_G + (size_t)i * FFn * Dn,
            pw + W_U + (size_t)i * FFn * Dn,
            pgh);

        hg_add_kernel<<<dim3(Dn / 64, Tn / 128), 256, HG_SMEM(64)>>>(
            pgh, pw + W_D + (size_t)i * Dn * FFn, ph, Dn, FFn);
    }

    rms_rows_kernel<0><<<Tn, 256>>>(ph, nw, out, nullptr);
}

// round 15
// speedup vs baseline: 1.5123x; 1.1056x over previous
#include <cuda_runtime.h>
#include <cuda_fp16.h>
#include <math.h>
#include <stdint.h>

constexpr int Tn = 2048, Dn = 1024, Hn = 16, KVn = 8, HDn = 128, FFn = 3072, Ln = 5;
constexpr float EPSf = 1e-6f;

// ---------------- scratch ----------------
__device__ float g_h [Tn * Dn];
__device__ float g_cos[Tn * 64];
__device__ float g_sin[Tn * 64];

__device__ __align__(16) __half g_xh  [Tn * Dn];
__device__ __align__(16) __half g_aoh [Tn * Hn * HDn];
__device__ __align__(16) __half g_gh  [Tn * FFn];
__device__ __align__(16) __half g_q16 [Tn * Hn * HDn];
__device__ __align__(16) __half g_k16 [KVn * Tn * HDn];
__device__ __align__(16) __half g_vt16[KVn * HDn * Tn];

constexpr size_t W_Q  = 0;
constexpr size_t W_K  = W_Q + (size_t)Ln * Hn * HDn * Dn;
constexpr size_t W_V  = W_K + (size_t)Ln * KVn * HDn * Dn;
constexpr size_t W_O  = W_V + (size_t)Ln * KVn * HDn * Dn;
constexpr size_t W_G  = W_O + (size_t)Ln * Dn * Hn * HDn;
constexpr size_t W_U  = W_G + (size_t)Ln * FFn * Dn;
constexpr size_t W_D  = W_U + (size_t)Ln * FFn * Dn;
constexpr size_t W_TOT= W_D + (size_t)Ln * Dn * FFn;
__device__ __align__(16) __half g_w[W_TOT];

// ---------------- PTX helpers ----------------
__device__ __forceinline__ uint32_t sptr(const void* p) {
    return (uint32_t)__cvta_generic_to_shared(p);
}
__device__ __forceinline__ void ldm_x4(uint32_t* r, uint32_t addr) {
    asm volatile("ldmatrix.sync.aligned.m8n8.x4.shared.b16 {%0,%1,%2,%3}, [%4];"
                 : "=r"(r[0]), "=r"(r[1]), "=r"(r[2]), "=r"(r[3]) : "r"(addr));
}
__device__ __forceinline__ void mma_f16(float* c, const uint32_t* a, uint32_t b0, uint32_t b1) {
    asm volatile("mma.sync.aligned.m16n8k16.row.col.f32.f16.f16.f32 "
                 "{%0,%1,%2,%3}, {%4,%5,%6,%7}, {%8,%9}, {%0,%1,%2,%3};"
                 : "+f"(c[0]), "+f"(c[1]), "+f"(c[2]), "+f"(c[3])
                 : "r"(a[0]), "r"(a[1]), "r"(a[2]), "r"(a[3]), "r"(b0), "r"(b1));
}
__device__ __forceinline__ void cp_async16(uint32_t dst, const void* src) {
    asm volatile("cp.async.ca.shared.global [%0], [%1], 16;" :: "r"(dst), "l"(src));
}
__device__ __forceinline__ void cp_commit() {
    asm volatile("cp.async.commit_group;" ::: "memory");
}
template <int N>
__device__ __forceinline__ void cp_wait() {
    asm volatile("cp.async.wait_group %0;" :: "n"(N) : "memory");
}
__device__ __forceinline__ uint32_t h2u(__half2 h) { return *(uint32_t*)&h; }

// ---------------- weight fp16 conversion ----------------
struct Cv7 {
    const float4* s[7];
    __half* d[7];
    int cum[8];
};
__global__ void conv7_kernel(Cv7 a) {
    int idx = blockIdx.x * 256 + threadIdx.x;
    if (idx >= a.cum[7]) return;
    int s = 0;
#pragma unroll
    for (int i = 0; i < 6; i++) s += (idx >= a.cum[i + 1]) ? 1 : 0;
    int off = idx - a.cum[s];
    float4 v = a.s[s][off];
    ((uint2*)a.d[s])[off] = make_uint2(h2u(__floats2half2_rn(v.x, v.y)),
                                       h2u(__floats2half2_rn(v.z, v.w)));
}

// ---------------- RoPE tables ----------------
__global__ void rope_tables_kernel() {
    int t = blockIdx.x, j = threadIdx.x;
    float inv = 1.0f / powf(1.0e6f, (float)j * (1.0f / 64.0f));
    g_cos[t * 64 + j] = cosf((float)t * inv);
    g_sin[t * 64 + j] = sinf((float)t * inv);
}

// ---------------- RMSNorm rows ----------------
template <int HALF>
__global__ void rms_rows_kernel(const float* __restrict__ in,
                                const float* __restrict__ w,
                                float* __restrict__ out,
                                __half* __restrict__ oh) {
    int t = blockIdx.x;
    const float4* ip = (const float4*)(in + (size_t)t * Dn);
    const float4* wp = (const float4*)w;
    float4 v = ip[threadIdx.x];
    float s = v.x * v.x + v.y * v.y + v.z * v.z + v.w * v.w;
#pragma unroll
    for (int off = 16; off; off >>= 1) s += __shfl_xor_sync(0xffffffffu, s, off);
    __shared__ float ws[8];
    if ((threadIdx.x & 31) == 0) ws[threadIdx.x >> 5] = s;
    __syncthreads();
    float tot = 0.f;
#pragma unroll
    for (int i = 0; i < 8; i++) tot += ws[i];
    float r = rsqrtf(tot * (1.0f / (float)Dn) + EPSf);
    float4 wv = wp[threadIdx.x];
    float4 o = make_float4(v.x * r * wv.x, v.y * r * wv.y, v.z * r * wv.z, v.w * r * wv.w);
    if (HALF) {
        ((uint2*)(oh + (size_t)t * Dn))[threadIdx.x] =
            make_uint2(h2u(__floats2half2_rn(o.x, o.y)),
                       h2u(__floats2half2_rn(o.z, o.w)));
    } else {
        ((float4*)(out + (size_t)t * Dn))[threadIdx.x] = o;
    }
}

// ---------------- fp16 tensor-core GEMM NT (2-stage) with fused epilogues ----------------
// EPI: 0 = fp32 +=ADD, 2 = V (fp32 vals + fp16 V^T), 3 = Q norm+rope, 4 = K norm+rope
constexpr int HROWB = 144;
constexpr int ASTB  = 128 * HROWB;
#define HG_SMEM(BN) (2 * (128 + (BN)) * HROWB)

template <int ADD, int BN, int EPI>
__device__ __forceinline__ void hgemm_body(const __half* __restrict__ A,
                                           const __half* __restrict__ B,
                                           float* __restrict__ C,
                                           __half* __restrict__ Ch,
                                           const float* __restrict__ wnorm,
                                           int N, int K, int m0, int n0,
                                           char* smem) {
    constexpr int BSTB = BN * HROWB;
    constexpr int NT2  = BN / 32;
    const int tid = threadIdx.x, lane = tid & 31, wid = tid >> 5;
    const int wm = wid & 3, wn = wid >> 2;

    const __half* Ag = A + (size_t)m0 * K;
    const __half* Bg = B + (size_t)n0 * K;
    const uint32_t sA = sptr(smem);
    const uint32_t sB = sA + 2 * ASTB;

    float acc[2][BN / 16][4];
#pragma unroll
    for (int i = 0; i < 2; i++)
#pragma unroll
        for (int j = 0; j < BN / 16; j++)
#pragma unroll
            for (int q = 0; q < 4; q++) acc[i][j][q] = 0.f;

    const int frow = ((lane >> 3) & 1) * 8 + (lane & 7);
    const int fcol = (lane >> 4) * 16;
    const int nk = K >> 6;

    auto stage = [&](int st, int kt) {
        const __half* Ak = Ag + (size_t)kt * 64;
        const __half* Bk = Bg + (size_t)kt * 64;
        uint32_t da = sA + st * ASTB;
        uint32_t db = sB + st * BSTB;
#pragma unroll
        for (int it = 0; it < 4; ++it) {
            int ch = tid + it * 256;
            int row = ch >> 3, c16 = ch & 7;
            cp_async16(da + row * HROWB + c16 * 16, Ak + (size_t)row * K + c16 * 8);
        }
#pragma unroll
        for (int it = 0; it < BN / 32; ++it) {
            int ch = tid + it * 256;
            int row = ch >> 3, c16 = ch & 7;
            cp_async16(db + row * HROWB + c16 * 16, Bk + (size_t)row * K + c16 * 8);
        }
        cp_commit();
    };

    stage(0, 0);

    for (int i = 0; i < nk; ++i) {
        cp_wait<0>();
        __syncthreads();
        if (i + 1 < nk) stage((i + 1) & 1, i + 1);

        const int cur = i & 1;
        const uint32_t aaddr = sA + cur * ASTB + (wm * 32 + frow) * HROWB + fcol;
        const uint32_t baddr = sB + cur * BSTB + (wn * (BN / 2) + frow) * HROWB + fcol;
#pragma unroll
        for (int ks = 0; ks < 4; ++ks) {
            uint32_t af[2][4];
            ldm_x4(af[0], aaddr + ks * 32);
            ldm_x4(af[1], aaddr + 16 * HROWB + ks * 32);
#pragma unroll
            for (int n2 = 0; n2 < NT2; ++n2) {
                uint32_t bf[4];
                ldm_x4(bf, baddr + n2 * 16 * HROWB + ks * 32);
#pragma unroll
                for (int mt = 0; mt < 2; ++mt) {
                    mma_f16(acc[mt][n2 * 2],     af[mt], bf[0], bf[2]);
                    mma_f16(acc[mt][n2 * 2 + 1], af[mt], bf[1], bf[3]);
                }
            }
        }
    }

    const int row0 = m0 + wm * 32 + (lane >> 2);
    const int col0 = n0 + wn * (BN / 2) + (lane & 3) * 2;

    if (EPI == 3 || EPI == 4) {
        // ---- fused per-head RMSNorm + RoPE (BN == 128; one head per CTA) ----
        __syncthreads();
        float* sE = (float*)smem;     // [128][132] fp32
        const int lr = wm * 32 + (lane >> 2);
        const int lc = wn * 64 + (lane & 3) * 2;
#pragma unroll
        for (int mt = 0; mt < 2; ++mt)
#pragma unroll
            for (int nt = 0; nt < BN / 16; ++nt) {
                int r = lr + mt * 16, c = lc + nt * 8;
                *(float2*)&sE[r * 132 + c] = make_float2(acc[mt][nt][0], acc[mt][nt][1]);
                *(float2*)&sE[(r + 8) * 132 + c] = make_float2(acc[mt][nt][2], acc[mt][nt][3]);
            }
        __syncthreads();

        const int head = n0 >> 7;
        const int d0 = lane * 4;
        const int dd = (d0 < 64) ? d0 + 64 : d0 - 64;
        const float sgn = (d0 < 64) ? -1.f : 1.f;
        const float w0 = wnorm[d0], w1 = wnorm[d0 + 1], w2 = wnorm[d0 + 2], w3 = wnorm[d0 + 3];
        const float wo0 = wnorm[dd], wo1 = wnorm[dd + 1], wo2 = wnorm[dd + 2], wo3 = wnorm[dd + 3];
        const int j0 = d0 & 63;

        for (int it = 0; it < 16; ++it) {
            int row = wid * 16 + it;
            int t = m0 + row;
            float4 v  = *(float4*)&sE[row * 132 + d0];
            float4 vo = *(float4*)&sE[row * 132 + dd];
            float ss = v.x * v.x + v.y * v.y + v.z * v.z + v.w * v.w;
#pragma unroll
            for (int o = 16; o; o >>= 1) ss += __shfl_xor_sync(0xffffffffu, ss, o);
            float rr = rsqrtf(ss * (1.0f / 128.f) + EPSf);
            float c0 = g_cos[t * 64 + j0],     s0 = g_sin[t * 64 + j0];
            float c1 = g_cos[t * 64 + j0 + 1], s1 = g_sin[t * 64 + j0 + 1];
            float c2 = g_cos[t * 64 + j0 + 2], s2 = g_sin[t * 64 + j0 + 2];
            float c3 = g_cos[t * 64 + j0 + 3], s3 = g_sin[t * 64 + j0 + 3];
            float o0 = v.x * rr * w0 * c0 + sgn * vo.x * rr * wo0 * s0;
            float o1 = v.y * rr * w1 * c1 + sgn * vo.y * rr * wo1 * s1;
            float o2 = v.z * rr * w2 * c2 + sgn * vo.z * rr * wo2 * s2;
            float o3 = v.w * rr * w3 * c3 + sgn * vo.w * rr * wo3 * s3;
            if (EPI == 3) {
                constexpr float sc = 0.0883883476483184f;
                uint2 p = make_uint2(h2u(__floats2half2_rn(o0 * sc, o1 * sc)),
                                     h2u(__floats2half2_rn(o2 * sc, o3 * sc)));
                *(uint2*)&Ch[((size_t)t * Hn + head) * HDn + d0] = p;
            } else {
                size_t idx = ((size_t)head * Tn + t) * HDn + d0;
                *(float4*)&C[idx] = make_float4(o0, o1, o2, o3);
                *(uint2*)&Ch[idx] = make_uint2(h2u(__floats2half2_rn(o0, o1)),
                                               h2u(__floats2half2_rn(o2, o3)));
            }
        }
        return;
    }

#pragma unroll
    for (int mt = 0; mt < 2; ++mt)
#pragma unroll
        for (int nt = 0; nt < BN / 16; ++nt) {
            int r = row0 + mt * 16;
            int c = col0 + nt * 8;
            float2 v0 = make_float2(acc[mt][nt][0], acc[mt][nt][1]);
            float2 v1 = make_float2(acc[mt][nt][2], acc[mt][nt][3]);
            if (EPI == 2) {
                *(float2*)&C[((size_t)(c >> 7) * Tn + r) * HDn + (c & 127)] = v0;
                *(float2*)&C[((size_t)(c >> 7) * Tn + (r + 8)) * HDn + (c & 127)] = v1;
                size_t vb = ((size_t)(c >> 7) * HDn + (c & 127)) * Tn;
                Ch[vb + r]          = __float2half(v0.x);
                Ch[vb + Tn + r]     = __float2half(v0.y);
                Ch[vb + r + 8]      = __float2half(v1.x);
                Ch[vb + Tn + r + 8] = __float2half(v1.y);
            } else {
                float2* p0 = (float2*)&C[(size_t)r * N + c];
                float2* p1 = (float2*)&C[(size_t)(r + 8) * N + c];
                if (ADD) {
                    float2 o0 = *p0, o1 = *p1;
                    v0.x += o0.x; v0.y += o0.y; v1.x += o1.x; v1.y += o1.y;
                }
                *p0 = v0;
                *p1 = v1;
            }
        }
}

// fused QKV + norm/rope: grid.x = 16 (q) + 8 (k) + 8 (v)
__global__ __launch_bounds__(256, 2) void hg_qkv_kernel(
    const __half* __restrict__ xh,
    const __half* __restrict__ wq, const __half* __restrict__ wk, const __half* __restrict__ wv,
    const float* __restrict__ qn, const float* __restrict__ kn,
    __half* __restrict__ q16, float* __restrict__ klayer, __half* __restrict__ k16,
    float* __restrict__ vlayer, __half* __restrict__ vt16) {
    extern __shared__ char smem[];
    int bx = blockIdx.x, m0 = blockIdx.y * 128;
    if (bx < 16)
        hgemm_body<0, 128, 3>(xh, wq, nullptr, q16, qn, Hn * HDn, Dn, m0, bx * 128, smem);
    else if (bx < 24)
        hgemm_body<0, 128, 4>(xh, wk, klayer, k16, kn, KVn * HDn, Dn, m0, (bx - 16) * 128, smem);
    else
        hgemm_body<0, 128, 2>(xh, wv, vlayer, vt16, nullptr, KVn * HDn, Dn, m0, (bx - 24) * 128, smem);
}

// gate+up in one CTA with fused silu(g)*u epilogue; grid (FFn/64, Tn/128)
__global__ __launch_bounds__(256, 2) void hg_gusilu_kernel(
    const __half* __restrict__ xh,
    const __half* __restrict__ wg, const __half* __restrict__ wu,
    __half* __restrict__ out) {
    extern __shared__ char smem[];
    const int m0 = blockIdx.y * 128, n0 = blockIdx.x * 64;
    const int tid = threadIdx.x, lane = tid & 31, wid = tid >> 5;
    const int wm = wid & 3, wn = wid >> 2;

    const __half* Ag = xh + (size_t)m0 * Dn;
    const __half* Gg = wg + (size_t)n0 * Dn;
    const __half* Ug = wu + (size_t)n0 * Dn;
    const uint32_t sA = sptr(smem);
    const uint32_t sB = sA + 2 * ASTB;
    constexpr int BSTB = 128 * HROWB;

    float ag[2][4][4], au[2][4][4];
#pragma unroll
    for (int i = 0; i < 2; i++)
#pragma unroll
        for (int j = 0; j < 4; j++)
#pragma unroll
            for (int q = 0; q < 4; q++) { ag[i][j][q] = 0.f; au[i][j][q] = 0.f; }

    const int frow = ((lane >> 3) & 1) * 8 + (lane & 7);
    const int fcol = (lane >> 4) * 16;
    const int nk = Dn >> 6;

    auto stage = [&](int st, int kt) {
        const __half* Ak = Ag + (size_t)kt * 64;
        const __half* Gk = Gg + (size_t)kt * 64;
        const __half* Uk = Ug + (size_t)kt * 64;
        uint32_t da = sA + st * ASTB;
        uint32_t db = sB + st * BSTB;
#pragma unroll
        for (int it = 0; it < 4; ++it) {
            int ch = tid + it * 256;
            int row = ch >> 3, c16 = ch & 7;
            cp_async16(da + row * HROWB + c16 * 16, Ak + (size_t)row * Dn + c16 * 8);
        }
#pragma unroll
        for (int it = 0; it < 2; ++it) {
            int ch = tid + it * 256;
            int row = ch >> 3, c16 = ch & 7;
            cp_async16(db + row * HROWB + c16 * 16, Gk + (size_t)row * Dn + c16 * 8);
            cp_async16(db + (64 + row) * HROWB + c16 * 16, Uk + (size_t)row * Dn + c16 * 8);
        }
        cp_commit();
    };

    stage(0, 0);

    for (int i = 0; i < nk; ++i) {
        cp_wait<0>();
        __syncthreads();
        if (i + 1 < nk) stage((i + 1) & 1, i + 1);

        const int cur = i & 1;
        const uint32_t aaddr = sA + cur * ASTB + (wm * 32 + frow) * HROWB + fcol;
        const uint32_t gaddr = sB + cur * BSTB + (wn * 32 + frow) * HROWB + fcol;
        const uint32_t uaddr = gaddr + 64 * HROWB;
#pragma unroll
        for (int ks = 0; ks < 4; ++ks) {
            uint32_t af[2][4];
            ldm_x4(af[0], aaddr + ks * 32);
            ldm_x4(af[1], aaddr + 16 * HROWB + ks * 32);
#pragma unroll
            for (int n2 = 0; n2 < 2; ++n2) {
                uint32_t bg[4], bu[4];
                ldm_x4(bg, gaddr + n2 * 16 * HROWB + ks * 32);
                ldm_x4(bu, uaddr + n2 * 16 * HROWB + ks * 32);
#pragma unroll
                for (int mt = 0; mt < 2; ++mt) {
                    mma_f16(ag[mt][n2 * 2],     af[mt], bg[0], bg[2]);
                    mma_f16(ag[mt][n2 * 2 + 1], af[mt], bg[1], bg[3]);
                    mma_f16(au[mt][n2 * 2],     af[mt], bu[0], bu[2]);
                    mma_f16(au[mt][n2 * 2 + 1], af[mt], bu[1], bu[3]);
                }
            }
        }
    }

    const int row0 = m0 + wm * 32 + (lane >> 2);
    const int col0 = n0 + wn * 32 + (lane & 3) * 2;
#pragma unroll
    for (int mt = 0; mt < 2; ++mt)
#pragma unroll
        for (int nt = 0; nt < 4; ++nt) {
            int r = row0 + mt * 16;
            int c = col0 + nt * 8;
            float g0 = ag[mt][nt][0], g1 = ag[mt][nt][1];
            float g2 = ag[mt][nt][2], g3 = ag[mt][nt][3];
            float r0 = g0 / (1.0f + __expf(-g0)) * au[mt][nt][0];
            float r1 = g1 / (1.0f + __expf(-g1)) * au[mt][nt][1];
            float r2 = g2 / (1.0f + __expf(-g2)) * au[mt][nt][2];
            float r3 = g3 / (1.0f + __expf(-g3)) * au[mt][nt][3];
            *(__half2*)&out[(size_t)r * FFn + c]       = __floats2half2_rn(r0, r1);
            *(__half2*)&out[(size_t)(r + 8) * FFn + c] = __floats2half2_rn(r2, r3);
        }
}

__global__ __launch_bounds__(256, 2) void hg_add_kernel(
    const __half* __restrict__ a, const __half* __restrict__ b,
    float* __restrict__ C, int N, int K) {
    extern __shared__ char smem[];
    hgemm_body<1, 64, 0>(a, b, C, nullptr, nullptr, N, K, blockIdx.y * 128, blockIdx.x * 64, smem);
}

// ---------------- fp16 flash attention with cp.async pipelined K/V ----------------
// grid (Hn, Tn/128): heads scan fastest so every head's heaviest q-tile lands in wave 1.
constexpr int SKH = 136, SVH = 72, SPH = 72;
constexpr int KTB = 64 * SKH * 2;
constexpr int VTB = 128 * SVH * 2;
constexpr int QSTB = 128 * SKH * 2;
constexpr int ATTN_SMEM = QSTB + 2 * KTB + 2 * VTB;  // 106496

__global__ __launch_bounds__(256) void attn_h_kernel(const __half* __restrict__ Q16,
                                                     const __half* __restrict__ K16,
                                                     const __half* __restrict__ VT16,
                                                     __half* __restrict__ AO) {
    extern __shared__ char smraw[];
    const uint32_t sQ = sptr(smraw);
    const uint32_t sKb = sQ + QSTB;
    const uint32_t sVb = sKb + 2 * KTB;

    const int h = blockIdx.x;
    const int qt0 = (gridDim.y - 1 - blockIdx.y) * 128;  // heavy q-tiles launch first
    const int kv = h >> 1;
    const int tid = threadIdx.x, lane = tid & 31, wid = tid >> 5;
    const int frow = ((lane >> 3) & 1) * 8 + (lane & 7);
    const int fcol = (lane >> 4) * 16;
    const int r0 = lane >> 2, c0 = (lane & 3) * 2;
    const int nkt = (qt0 >> 6) + 2;

    const char* kbase = (const char*)(K16 + (size_t)kv * Tn * HDn);
    const char* vbase = (const char*)(VT16 + (size_t)kv * HDn * Tn);

    auto stageKV = [&](int kt) {
        const int kt0 = kt << 6;
        uint32_t kb = sKb + (kt & 1) * KTB;
        uint32_t vb = sVb + (kt & 1) * VTB;
        const char* ks = kbase + (size_t)kt0 * (HDn * 2);
#pragma unroll
        for (int it = 0; it < 4; ++it) {
            int ch = tid + it * 256;
            int row = ch >> 4, c = ch & 15;
            cp_async16(kb + row * (SKH * 2) + c * 16, ks + (size_t)row * 256 + c * 16);
        }
        const char* vs = vbase + (size_t)kt0 * 2;
#pragma unroll
        for (int it = 0; it < 4; ++it) {
            int ch = tid + it * 256;
            int row = ch >> 3, c = ch & 7;
            cp_async16(vb + row * (SVH * 2) + c * 16, vs + (size_t)row * (Tn * 2) + c * 16);
        }
        cp_commit();
    };

    {
        const char* qs = (const char*)(Q16 + ((size_t)qt0 * Hn + h) * HDn);
#pragma unroll
        for (int it = 0; it < 8; ++it) {
            int ch = tid + it * 256;
            int row = ch >> 4, c = ch & 15;
            cp_async16(sQ + row * (SKH * 2) + c * 16,
                       qs + (size_t)row * (Hn * HDn * 2) + c * 16);
        }
        cp_commit();
    }
    stageKV(0);

    cp_wait<1>();
    __syncthreads();
    uint32_t qf[8][4];
    {
        uint32_t qaddr = sQ + (wid * 16 + frow) * (SKH * 2) + fcol;
#pragma unroll
        for (int ks = 0; ks < 8; ++ks) ldm_x4(qf[ks], qaddr + ks * 32);
    }

    float o[16][4];
#pragma unroll
    for (int i = 0; i < 16; i++)
#pragma unroll
        for (int j = 0; j < 4; j++) o[i][j] = 0.f;
    float mreg[2] = {-1e30f, -1e30f}, lreg[2] = {0.f, 0.f};

    const uint32_t myP = sQ + wid * 16 * (SPH * 2);
    const uint32_t paddr = myP + frow * (SPH * 2) + fcol;

    for (int kt = 0; kt < nkt; ++kt) {
        const int kt0 = kt << 6;
        cp_wait<0>();
        __syncthreads();
        if (kt + 1 < nkt) stageKV(kt + 1);

        const uint32_t kaddr = sKb + (kt & 1) * KTB + frow * (SKH * 2) + fcol;
        const uint32_t vaddr = sVb + (kt & 1) * VTB + frow * (SVH * 2) + fcol;

        float s[8][4];
#pragma unroll
        for (int i = 0; i < 8; i++)
#pragma unroll
            for (int j = 0; j < 4; j++) s[i][j] = 0.f;
#pragma unroll
        for (int ks = 0; ks < 8; ++ks) {
#pragma unroll
            for (int ntp = 0; ntp < 4; ++ntp) {
                uint32_t bf[4];
                ldm_x4(bf, kaddr + ntp * 16 * (SKH * 2) + ks * 32);
                mma_f16(s[ntp * 2],     qf[ks], bf[0], bf[2]);
                mma_f16(s[ntp * 2 + 1], qf[ks], bf[1], bf[3]);
            }
        }

        if (kt >= nkt - 2) {
            int rowg = qt0 + wid * 16 + r0;
#pragma unroll
            for (int nt = 0; nt < 8; ++nt) {
                int colg = kt0 + nt * 8 + c0;
                if (colg > rowg)          s[nt][0] = -1e30f;
                if (colg + 1 > rowg)      s[nt][1] = -1e30f;
                if (colg > rowg + 8)      s[nt][2] = -1e30f;
                if (colg + 1 > rowg + 8)  s[nt][3] = -1e30f;
            }
        }

#pragma unroll
        for (int hf = 0; hf < 2; ++hf) {
            float rm = -1e30f;
#pragma unroll
            for (int nt = 0; nt < 8; ++nt)
                rm = fmaxf(rm, fmaxf(s[nt][2 * hf], s[nt][2 * hf + 1]));
            rm = fmaxf(rm, __shfl_xor_sync(0xffffffffu, rm, 1));
            rm = fmaxf(rm, __shfl_xor_sync(0xffffffffu, rm, 2));
            float mn = fmaxf(mreg[hf], rm);
            float corr = __expf(mreg[hf] - mn);
            mreg[hf] = mn;
            float su = 0.f;
#pragma unroll
            for (int nt = 0; nt < 8; ++nt) {
                float e0 = __expf(s[nt][2 * hf] - mn);
                float e1 = __expf(s[nt][2 * hf + 1] - mn);
                s[nt][2 * hf] = e0;
                s[nt][2 * hf + 1] = e1;
                su += e0 + e1;
            }
            su += __shfl_xor_sync(0xffffffffu, su, 1);
            su += __shfl_xor_sync(0xffffffffu, su, 2);
            lreg[hf] = lreg[hf] * corr + su;
#pragma unroll
            for (int nt = 0; nt < 16; ++nt) {
                o[nt][2 * hf] *= corr;
                o[nt][2 * hf + 1] *= corr;
            }
        }

#pragma unroll
        for (int nt = 0; nt < 8; ++nt) {
            *(uint32_t*)((char*)smraw + (myP - sQ) + r0 * (SPH * 2) + (nt * 8 + c0) * 2) =
                h2u(__floats2half2_rn(s[nt][0], s[nt][1]));
            *(uint32_t*)((char*)smraw + (myP - sQ) + (r0 + 8) * (SPH * 2) + (nt * 8 + c0) * 2) =
                h2u(__floats2half2_rn(s[nt][2], s[nt][3]));
        }
        __syncwarp();

#pragma unroll
        for (int ks = 0; ks < 4; ++ks) {
            uint32_t pf[4];
            ldm_x4(pf, paddr + ks * 32);
#pragma unroll
            for (int np = 0; np < 8; ++np) {
                uint32_t bf[4];
                ldm_x4(bf, vaddr + np * 16 * (SVH * 2) + ks * 32);
                mma_f16(o[2 * np],     pf, bf[0], bf[2]);
                mma_f16(o[2 * np + 1], pf, bf[1], bf[3]);
            }
        }
    }

    float inv0 = 1.0f / lreg[0], inv1 = 1.0f / lreg[1];
    int rowg = qt0 + wid * 16 + r0;
#pragma unroll
    for (int nt = 0; nt < 16; ++nt) {
        size_t base = (size_t)h * HDn + nt * 8 + c0;
        *(__half2*)&AO[(size_t)rowg * (Hn * HDn) + base] =
            __floats2half2_rn(o[nt][0] * inv0, o[nt][1] * inv0);
        *(__half2*)&AO[(size_t)(rowg + 8) * (Hn * HDn) + base] =
            __floats2half2_rn(o[nt][2] * inv1, o[nt][3] * inv1);
    }
}

// ---------------- host orchestration ----------------
extern "C" void kernel_launch(void* const* d_in, const int* in_sizes, int n_in,
                              void* d_out, int out_size) {
    const float* emb = (const float*)d_in[0];
    const float* ln1 = (const float*)d_in[1];
    const float* qw  = (const float*)d_in[2];
    const float* kw  = (const float*)d_in[3];
    const float* vw  = (const float*)d_in[4];
    const float* qn  = (const float*)d_in[5];
    const float* kn  = (const float*)d_in[6];
    const float* ow  = (const float*)d_in[7];
    const float* ln2 = (const float*)d_in[8];
    const float* gw  = (const float*)d_in[9];
    const float* uw  = (const float*)d_in[10];
    const float* dw  = (const float*)d_in[11];
    const float* nw  = (const float*)d_in[12];

    float* out  = (float*)d_out;
    float* keys = out + (size_t)Tn * Dn;
    float* vals = keys + (size_t)Ln * KVn * Tn * HDn;

    float* ph;
    __half *pxh, *paoh, *pgh, *pw, *pq16, *pk16, *pvt16;
    cudaGetSymbolAddress((void**)&ph,    g_h);
    cudaGetSymbolAddress((void**)&pxh,   g_xh);
    cudaGetSymbolAddress((void**)&paoh,  g_aoh);
    cudaGetSymbolAddress((void**)&pgh,   g_gh);
    cudaGetSymbolAddress((void**)&pw,    g_w);
    cudaGetSymbolAddress((void**)&pq16,  g_q16);
    cudaGetSymbolAddress((void**)&pk16,  g_k16);
    cudaGetSymbolAddress((void**)&pvt16, g_vt16);

    cudaFuncSetAttribute(attn_h_kernel, cudaFuncAttributeMaxDynamicSharedMemorySize, ATTN_SMEM);
    cudaFuncSetAttribute(hg_qkv_kernel, cudaFuncAttributeMaxDynamicSharedMemorySize, HG_SMEM(128));
    cudaFuncSetAttribute(hg_gusilu_kernel, cudaFuncAttributeMaxDynamicSharedMemorySize, HG_SMEM(128));
    cudaFuncSetAttribute(hg_add_kernel, cudaFuncAttributeMaxDynamicSharedMemorySize, HG_SMEM(64));

    {
        Cv7 a;
        size_t offs[7] = { W_Q, W_K, W_V, W_O, W_G, W_U, W_D };
        const float* srcs[7] = { qw, kw, vw, ow, gw, uw, dw };
        size_t ns[7] = {
            (size_t)Ln * Hn * HDn * Dn, (size_t)Ln * KVn * HDn * Dn,
            (size_t)Ln * KVn * HDn * Dn, (size_t)Ln * Dn * Hn * HDn,
            (size_t)Ln * FFn * Dn, (size_t)Ln * FFn * Dn, (size_t)Ln * Dn * FFn };
        int cum = 0;
        for (int i = 0; i < 7; i++) {
            a.s[i] = (const float4*)srcs[i];
            a.d[i] = pw + offs[i];
            a.cum[i] = cum;
            cum += (int)(ns[i] / 4);
        }
        a.cum[7] = cum;
        conv7_kernel<<<(cum + 255) / 256, 256>>>(a);
    }

    cudaMemcpyAsync(ph, emb, sizeof(float) * Tn * Dn, cudaMemcpyDeviceToDevice);
    rope_tables_kernel<<<Tn, 64>>>();

    for (int i = 0; i < Ln; ++i) {
        float* klayer = keys + (size_t)i * KVn * Tn * HDn;
        float* vlayer = vals + (size_t)i * KVn * Tn * HDn;

        rms_rows_kernel<1><<<Tn, 256>>>(ph, ln1 + (size_t)i * Dn, nullptr, pxh);

        hg_qkv_kernel<<<dim3(32, Tn / 128), 256, HG_SMEM(128)>>>(
            pxh,
            pw + W_Q + (size_t)i * (Hn * HDn) * Dn,
            pw + W_K + (size_t)i * (KVn * HDn) * Dn,
            pw + W_V + (size_t)i * (KVn * HDn) * Dn,
            qn + (size_t)i * HDn, kn + (size_t)i * HDn,
            pq16, klayer, pk16, vlayer, pvt16);

        attn_h_kernel<<<dim3(Hn, Tn / 128), 256, ATTN_SMEM>>>(pq16, pk16, pvt16, paoh);

        hg_add_kernel<<<dim3(Dn / 64, Tn / 128), 256, HG_SMEM(64)>>>(
            paoh, pw + W_O + (size_t)i * Dn * (Hn * HDn), ph, Dn, Hn * HDn);

        rms_rows_kernel<1><<<Tn, 256>>>(ph, ln2 + (size_t)i * Dn, nullptr, pxh);

        hg_gusilu_kernel<<<dim3(FFn / 64, Tn / 128), 256, HG_SMEM(128)>>>(
            pxh,
            pw + W_G + (size_t)i * FFn * Dn,
            pw + W_U + (size_t)i * FFn * Dn,
            pgh);

        hg_add_kernel<<<dim3(Dn / 64, Tn / 128), 256, HG_SMEM(64)>>>(
            pgh, pw + W_D + (size_t)i * Dn * FFn, ph, Dn, FFn);
    }

    rms_rows_kernel<0><<<Tn, 256>>>(ph, nw, out, nullptr);
}